// round 1
// baseline (speedup 1.0000x reference)
#include <cuda_runtime.h>
#include <math.h>

// ---------------- problem constants ----------------
#define Bn    2
#define Sn    2048
#define HIDn  2048
#define Hn    16
#define Dn    128
#define RANKn 512
#define BSn   (Bn*Sn)        // 4096
#define KVAN  (RANKn+Dn)     // 640
#define HDn   (Hn*Dn)        // 2048

#define MSCALE_F    1.2772588722239781f   // 0.1*ln(131072/8192)+1
#define ATTN_SCALE  0.08838834764831845f  // 1/sqrt(128)

// ---------------- scratch (device globals; no allocation allowed) ----------------
__device__ float g_q[(size_t)BSn*HDn];        // q proj, rope'd in place
__device__ float g_kva[(size_t)BSn*KVAN];     // kv_a proj
__device__ float g_ckv[(size_t)BSn*RANKn];    // rmsnormed c_kv
__device__ float g_kv[(size_t)BSn*Hn*2*Dn];   // kv_b proj
__device__ float g_k[(size_t)BSn*HDn];        // k_nope + k_rope
__device__ float g_v[(size_t)BSn*HDn];        // v
__device__ float g_krope[(size_t)BSn*Dn];     // rope'd shared k_rope
__device__ float g_attn[(size_t)BSn*HDn];     // attention output
__device__ float g_invfreq[Dn/2];

// ---------------- YaRN inv_freq ----------------
__global__ void init_invfreq_kernel() {
    int i = threadIdx.x;
    if (i >= Dn/2) return;
    const double base = 500000.0;
    const double two_pi = 6.283185307179586;
    double pf = exp(((double)(2*i) / (double)Dn) * log(base));
    double extrap = 1.0 / pf;
    double interp = 1.0 / (16.0 * pf);   // scaling = 131072/8192 = 16
    double lowf  = floor((double)Dn * log(8192.0 / (32.0 * two_pi)) / (2.0 * log(base)));
    double highf = ceil ((double)Dn * log(8192.0 / ( 1.0 * two_pi)) / (2.0 * log(base)));
    if (lowf < 0.0) lowf = 0.0;
    if (highf > (double)(Dn-1)) highf = (double)(Dn-1);
    double denom = highf - lowf;
    if (denom < 1.0) denom = 1.0;
    double sm = ((double)i - lowf) / denom;
    sm = fmin(fmax(sm, 0.0), 1.0);
    g_invfreq[i] = (float)((1.0 - sm) * interp + sm * extrap);
}

// ---------------- fp32 GEMM: C[M,N] = A[M,K] @ B[K,N] ----------------
// 128x128 tile, BK=16, 256 threads, 8x8 per thread. All dims here are
// multiples of the tile sizes (M=4096; N in {640,2048,4096}; K in {512,2048}).
__global__ __launch_bounds__(256) void gemm_f32(const float* __restrict__ A,
                                                const float* __restrict__ Bm,
                                                float* __restrict__ C,
                                                int M, int N, int K) {
    __shared__ float As[16][128];
    __shared__ float Bs[16][128];
    int tid = threadIdx.x;
    int bx = blockIdx.x, by = blockIdx.y;
    int tx = tid & 15, ty = tid >> 4;
    int ar = tid >> 2;            // 0..63
    int ac = (tid & 3) << 2;      // 0,4,8,12
    int br = tid >> 5;            // 0..7
    int bc = (tid & 31) << 2;     // 0..124

    const float* Ap = A + (size_t)(by*128 + ar) * K + ac;
    const float* Bp = Bm + (size_t)br * N + (size_t)bx*128 + bc;

    float acc[8][8];
    #pragma unroll
    for (int i = 0; i < 8; i++)
        #pragma unroll
        for (int j = 0; j < 8; j++) acc[i][j] = 0.f;

    for (int kt = 0; kt < K; kt += 16) {
        float4 a0 = *(const float4*)(Ap + kt);
        float4 a1 = *(const float4*)(Ap + (size_t)64*K + kt);
        float4 b0 = *(const float4*)(Bp + (size_t)kt*N);
        float4 b1 = *(const float4*)(Bp + (size_t)(kt+8)*N);
        __syncthreads();
        As[ac+0][ar] = a0.x; As[ac+1][ar] = a0.y; As[ac+2][ar] = a0.z; As[ac+3][ar] = a0.w;
        As[ac+0][ar+64] = a1.x; As[ac+1][ar+64] = a1.y; As[ac+2][ar+64] = a1.z; As[ac+3][ar+64] = a1.w;
        *(float4*)&Bs[br][bc]   = b0;
        *(float4*)&Bs[br+8][bc] = b1;
        __syncthreads();
        #pragma unroll
        for (int k = 0; k < 16; k++) {
            float4 av0 = *(float4*)&As[k][ty*8];
            float4 av1 = *(float4*)&As[k][ty*8+4];
            float4 bv0 = *(float4*)&Bs[k][tx*8];
            float4 bv1 = *(float4*)&Bs[k][tx*8+4];
            float a[8]  = {av0.x,av0.y,av0.z,av0.w,av1.x,av1.y,av1.z,av1.w};
            float bb[8] = {bv0.x,bv0.y,bv0.z,bv0.w,bv1.x,bv1.y,bv1.z,bv1.w};
            #pragma unroll
            for (int i = 0; i < 8; i++)
                #pragma unroll
                for (int j = 0; j < 8; j++)
                    acc[i][j] = fmaf(a[i], bb[j], acc[i][j]);
        }
    }
    #pragma unroll
    for (int i = 0; i < 8; i++) {
        size_t row = (size_t)(by*128 + ty*8 + i);
        float* cp = C + row*N + (size_t)bx*128 + tx*8;
        *(float4*)cp     = make_float4(acc[i][0],acc[i][1],acc[i][2],acc[i][3]);
        *(float4*)(cp+4) = make_float4(acc[i][4],acc[i][5],acc[i][6],acc[i][7]);
    }
}

// ---------------- RMSNorm on c_kv (first 512 of kv_a rows) ----------------
__global__ __launch_bounds__(128) void rmsnorm_kernel(const float* __restrict__ w) {
    int row = blockIdx.x;
    const float* x = g_kva + (size_t)row * KVAN;
    float* y = g_ckv + (size_t)row * RANKn;
    int tid = threadIdx.x;
    float4 v = *(const float4*)&x[tid*4];
    float ss = v.x*v.x + v.y*v.y + v.z*v.z + v.w*v.w;
    #pragma unroll
    for (int off = 16; off >= 1; off >>= 1)
        ss += __shfl_xor_sync(0xffffffffu, ss, off);
    __shared__ float warp_s[4];
    if ((tid & 31) == 0) warp_s[tid >> 5] = ss;
    __syncthreads();
    float total = warp_s[0] + warp_s[1] + warp_s[2] + warp_s[3];
    float inv = rsqrtf(total * (1.0f/(float)RANKn) + 1e-6f);
    float4 wv = *(const float4*)&w[tid*4];
    *(float4*)&y[tid*4] = make_float4(v.x*wv.x*inv, v.y*wv.y*inv, v.z*wv.z*inv, v.w*wv.w*inv);
}

// ---------------- RoPE on q (in place). one (bs,h) row per 64 threads ----------------
__global__ __launch_bounds__(256) void rope_q_kernel(const int* __restrict__ pos_ids) {
    int t = blockIdx.x * 4 + (threadIdx.x >> 6);  // bs*H + h
    int d = threadIdx.x & 63;
    int bs = t >> 4;
    float p = (float)pos_ids[bs];
    float f = p * g_invfreq[d];
    float sv, cv;
    sincosf(f, &sv, &cv);
    cv *= MSCALE_F; sv *= MSCALE_F;
    float* q = g_q + (size_t)t * Dn;
    float x0 = q[d], x1 = q[d+64];
    q[d]    = x0*cv - x1*sv;
    q[d+64] = x1*cv + x0*sv;
}

// ---------------- RoPE on shared k_rope ----------------
__global__ __launch_bounds__(256) void rope_k_kernel(const int* __restrict__ pos_ids) {
    int bs = blockIdx.x * 4 + (threadIdx.x >> 6);
    int d = threadIdx.x & 63;
    float p = (float)pos_ids[bs];
    float f = p * g_invfreq[d];
    float sv, cv;
    sincosf(f, &sv, &cv);
    cv *= MSCALE_F; sv *= MSCALE_F;
    const float* kr = g_kva + (size_t)bs * KVAN + RANKn;
    float x0 = kr[d], x1 = kr[d+64];
    float* o = g_krope + (size_t)bs * Dn;
    o[d]    = x0*cv - x1*sv;
    o[d+64] = x1*cv + x0*sv;
}

// ---------------- split kv into k (nope+rope) and v ----------------
__global__ __launch_bounds__(256) void build_kv_kernel() {
    int idx = blockIdx.x * 256 + threadIdx.x;  // float4 index over BSn*HDn/4
    int bs  = idx >> 9;          // /(HDn/4 = 512)
    int rem = idx & 511;
    int h   = rem >> 5;
    int d4  = (rem & 31) << 2;
    float4 kn = *(const float4*)&g_kv[(size_t)bs*4096 + h*256 + d4];
    float4 vv = *(const float4*)&g_kv[(size_t)bs*4096 + h*256 + 128 + d4];
    float4 kr = *(const float4*)&g_krope[(size_t)bs*128 + d4];
    size_t o = (size_t)bs*HDn + h*Dn + d4;
    *(float4*)&g_k[o] = make_float4(kn.x+kr.x, kn.y+kr.y, kn.z+kr.z, kn.w+kr.w);
    *(float4*)&g_v[o] = vv;
}

// ---------------- causal flash attention (fp32 SIMT) ----------------
// grid = (S/64, B*H); block = 256 threads (16x16). BM=BN=64, D=128.
// Smem: QsT/KsT stored [d][row] with row-stride 68 (pad) for conflict-free LDS.128.
#define FLASH_SMEM_BYTES ((2*128*68 + 64*128 + 64*64) * 4)

__global__ __launch_bounds__(256) void flash_kernel() {
    extern __shared__ float smf[];
    float* QsT = smf;                 // [128][68]
    float* KsT = QsT + 128*68;        // [128][68]
    float* Vs  = KsT + 128*68;        // [64][128]
    float* Ps  = Vs + 64*128;         // [64][64]

    int tid = threadIdx.x;
    int qt  = blockIdx.x;
    int bh  = blockIdx.y;
    int b = bh >> 4, h = bh & 15;

    const float* qbase = g_q + ((size_t)(b*Sn + qt*64)) * HDn + h*Dn;
    #pragma unroll
    for (int i = 0; i < 8; i++) {
        int idx = tid + i*256;
        int r   = idx >> 5;
        int d4  = (idx & 31) << 2;
        float4 v = *(const float4*)&qbase[(size_t)r*HDn + d4];
        QsT[(d4+0)*68 + r] = v.x * ATTN_SCALE;
        QsT[(d4+1)*68 + r] = v.y * ATTN_SCALE;
        QsT[(d4+2)*68 + r] = v.z * ATTN_SCALE;
        QsT[(d4+3)*68 + r] = v.w * ATTN_SCALE;
    }

    int ty = tid >> 4, tx = tid & 15;
    float Oa[4][8];
    float mrow[4], lrow[4];
    #pragma unroll
    for (int i = 0; i < 4; i++) {
        mrow[i] = -1e30f; lrow[i] = 0.f;
        #pragma unroll
        for (int j = 0; j < 8; j++) Oa[i][j] = 0.f;
    }

    for (int kt = 0; kt <= qt; kt++) {
        __syncthreads();  // protect KsT/Vs/Ps from previous iteration's readers
        const float* kbase = g_k + ((size_t)(b*Sn + kt*64)) * HDn + h*Dn;
        const float* vbase = g_v + ((size_t)(b*Sn + kt*64)) * HDn + h*Dn;
        #pragma unroll
        for (int i = 0; i < 8; i++) {
            int idx = tid + i*256;
            int r   = idx >> 5;
            int d4  = (idx & 31) << 2;
            float4 kv = *(const float4*)&kbase[(size_t)r*HDn + d4];
            KsT[(d4+0)*68 + r] = kv.x;
            KsT[(d4+1)*68 + r] = kv.y;
            KsT[(d4+2)*68 + r] = kv.z;
            KsT[(d4+3)*68 + r] = kv.w;
            float4 vv = *(const float4*)&vbase[(size_t)r*HDn + d4];
            *(float4*)&Vs[r*128 + d4] = vv;
        }
        __syncthreads();

        // S = Q*scale @ K^T  (thread: rows ty*4.., cols tx*4..)
        float sacc[4][4];
        #pragma unroll
        for (int i = 0; i < 4; i++)
            #pragma unroll
            for (int j = 0; j < 4; j++) sacc[i][j] = 0.f;
        #pragma unroll 8
        for (int d = 0; d < 128; d++) {
            float4 qv = *(float4*)&QsT[d*68 + ty*4];
            float4 kv = *(float4*)&KsT[d*68 + tx*4];
            float qa[4] = {qv.x,qv.y,qv.z,qv.w};
            float ka[4] = {kv.x,kv.y,kv.z,kv.w};
            #pragma unroll
            for (int i = 0; i < 4; i++)
                #pragma unroll
                for (int j = 0; j < 4; j++)
                    sacc[i][j] = fmaf(qa[i], ka[j], sacc[i][j]);
        }

        if (kt == qt) {  // diagonal tile: mask k_pos > q_pos
            #pragma unroll
            for (int i = 0; i < 4; i++)
                #pragma unroll
                for (int j = 0; j < 4; j++)
                    if (tx*4 + j > ty*4 + i) sacc[i][j] = -1e30f;
        }

        // online softmax (row reductions across the 16 tx lanes of each half-warp)
        float corr[4], rs[4];
        #pragma unroll
        for (int i = 0; i < 4; i++) {
            float lm = fmaxf(fmaxf(sacc[i][0], sacc[i][1]), fmaxf(sacc[i][2], sacc[i][3]));
            #pragma unroll
            for (int off = 8; off >= 1; off >>= 1)
                lm = fmaxf(lm, __shfl_xor_sync(0xffffffffu, lm, off));
            float mn = fmaxf(mrow[i], lm);
            corr[i] = __expf(mrow[i] - mn);
            mrow[i] = mn;
            sacc[i][0] = __expf(sacc[i][0] - mn);
            sacc[i][1] = __expf(sacc[i][1] - mn);
            sacc[i][2] = __expf(sacc[i][2] - mn);
            sacc[i][3] = __expf(sacc[i][3] - mn);
            float r = sacc[i][0] + sacc[i][1] + sacc[i][2] + sacc[i][3];
            #pragma unroll
            for (int off = 8; off >= 1; off >>= 1)
                r += __shfl_xor_sync(0xffffffffu, r, off);
            rs[i] = r;
        }
        #pragma unroll
        for (int i = 0; i < 4; i++) {
            lrow[i] = lrow[i]*corr[i] + rs[i];
            #pragma unroll
            for (int j = 0; j < 8; j++) Oa[i][j] *= corr[i];
            *(float4*)&Ps[(ty*4+i)*64 + tx*4] =
                make_float4(sacc[i][0], sacc[i][1], sacc[i][2], sacc[i][3]);
        }
        __syncthreads();

        // O += P @ V  (thread: rows ty*4.., cols tx*8..)
        #pragma unroll 4
        for (int k0 = 0; k0 < 64; k0 += 4) {
            float pr[4][4];
            #pragma unroll
            for (int i = 0; i < 4; i++) {
                float4 t4 = *(float4*)&Ps[(ty*4+i)*64 + k0];
                pr[i][0]=t4.x; pr[i][1]=t4.y; pr[i][2]=t4.z; pr[i][3]=t4.w;
            }
            #pragma unroll
            for (int kk = 0; kk < 4; kk++) {
                float4 v0 = *(float4*)&Vs[(k0+kk)*128 + tx*8];
                float4 v1 = *(float4*)&Vs[(k0+kk)*128 + tx*8 + 4];
                float vb[8] = {v0.x,v0.y,v0.z,v0.w,v1.x,v1.y,v1.z,v1.w};
                #pragma unroll
                for (int i = 0; i < 4; i++)
                    #pragma unroll
                    for (int j = 0; j < 8; j++)
                        Oa[i][j] = fmaf(pr[i][kk], vb[j], Oa[i][j]);
            }
        }
    }

    // epilogue: out = O / (l + EPS)
    #pragma unroll
    for (int i = 0; i < 4; i++) {
        float inv = 1.0f / (lrow[i] + 1e-5f);
        size_t row = (size_t)(b*Sn + qt*64 + ty*4 + i);
        float* op = g_attn + row*HDn + h*Dn + tx*8;
        *(float4*)op     = make_float4(Oa[i][0]*inv, Oa[i][1]*inv, Oa[i][2]*inv, Oa[i][3]*inv);
        *(float4*)(op+4) = make_float4(Oa[i][4]*inv, Oa[i][5]*inv, Oa[i][6]*inv, Oa[i][7]*inv);
    }
}

// ---------------- launch ----------------
extern "C" void kernel_launch(void* const* d_in, const int* in_sizes, int n_in,
                              void* d_out, int out_size) {
    const float* hidden  = (const float*)d_in[0];
    const int*   pos_ids = (const int*)  d_in[1];
    const float* w_q     = (const float*)d_in[2];
    const float* w_kv_a  = (const float*)d_in[3];
    const float* w_kv_b  = (const float*)d_in[4];
    const float* w_o     = (const float*)d_in[5];
    const float* kv_ln_w = (const float*)d_in[6];
    float* out = (float*)d_out;

    float *pq, *pkva, *pckv, *pkv, *pattn;
    cudaGetSymbolAddress((void**)&pq,    g_q);
    cudaGetSymbolAddress((void**)&pkva,  g_kva);
    cudaGetSymbolAddress((void**)&pckv,  g_ckv);
    cudaGetSymbolAddress((void**)&pkv,   g_kv);
    cudaGetSymbolAddress((void**)&pattn, g_attn);

    cudaFuncSetAttribute(flash_kernel, cudaFuncAttributeMaxDynamicSharedMemorySize,
                         FLASH_SMEM_BYTES);

    init_invfreq_kernel<<<1, 64>>>();

    // q = hidden @ w_q : [4096, 2048]
    gemm_f32<<<dim3(HDn/128, BSn/128), 256>>>(hidden, w_q, pq, BSn, HDn, HIDn);
    // kv_a = hidden @ w_kv_a : [4096, 640]
    gemm_f32<<<dim3(KVAN/128, BSn/128), 256>>>(hidden, w_kv_a, pkva, BSn, KVAN, HIDn);

    rmsnorm_kernel<<<BSn, 128>>>(kv_ln_w);
    rope_k_kernel<<<BSn/4, 256>>>(pos_ids);

    // kv = ckv @ w_kv_b : [4096, 4096]
    gemm_f32<<<dim3((Hn*2*Dn)/128, BSn/128), 256>>>(pckv, w_kv_b, pkv, BSn, Hn*2*Dn, RANKn);

    rope_q_kernel<<<(BSn*Hn)/4, 256>>>(pos_ids);
    build_kv_kernel<<<(BSn*HDn/4)/256, 256>>>();

    flash_kernel<<<dim3(Sn/64, Bn*Hn), 256, FLASH_SMEM_BYTES>>>();

    // out = attn @ w_o : [4096, 2048]
    gemm_f32<<<dim3(HIDn/128, BSn/128), 256>>>(pattn, w_o, out, BSn, HIDn, HIDn);
}

// round 2
// speedup vs baseline: 2.8898x; 2.8898x over previous
#include <cuda_runtime.h>
#include <math.h>

// ---------------- problem constants ----------------
#define Bn    2
#define Sn    2048
#define HIDn  2048
#define Hn    16
#define Dn    128
#define RANKn 512
#define BSn   (Bn*Sn)        // 4096
#define KVAN  (RANKn+Dn)     // 640
#define HDn   (Hn*Dn)        // 2048

#define MSCALE_F    1.2772588722239781f   // 0.1*ln(131072/8192)+1
#define ATTN_SCALE  0.08838834764831845f  // 1/sqrt(128)

// ---------------- scratch ----------------
__device__ float g_q[(size_t)BSn*HDn];
__device__ float g_kva[(size_t)BSn*KVAN];
__device__ float g_ckv[(size_t)BSn*RANKn];
__device__ float g_kv[(size_t)BSn*Hn*2*Dn];
__device__ float g_k[(size_t)BSn*HDn];
__device__ float g_v[(size_t)BSn*HDn];
__device__ float g_krope[(size_t)BSn*Dn];
__device__ float g_attn[(size_t)BSn*HDn];
__device__ float g_invfreq[Dn/2];

// ---------------- tf32 helpers ----------------
__device__ __forceinline__ unsigned f2tf32(float x) {
    unsigned u;
    asm("cvt.rna.tf32.f32 %0, %1;" : "=r"(u) : "f"(x));
    return u;
}
__device__ __forceinline__ float f2tf32f(float x) { return __uint_as_float(f2tf32(x)); }

__device__ __forceinline__ void mma_tf32(float* c, const unsigned* a, const unsigned* b) {
    asm volatile(
        "mma.sync.aligned.m16n8k8.row.col.f32.tf32.tf32.f32 "
        "{%0,%1,%2,%3}, {%4,%5,%6,%7}, {%8,%9}, {%0,%1,%2,%3};"
        : "+f"(c[0]), "+f"(c[1]), "+f"(c[2]), "+f"(c[3])
        : "r"(a[0]), "r"(a[1]), "r"(a[2]), "r"(a[3]), "r"(b[0]), "r"(b[1]));
}

// ---------------- YaRN inv_freq ----------------
__global__ void init_invfreq_kernel() {
    int i = threadIdx.x;
    if (i >= Dn/2) return;
    const double base = 500000.0;
    const double two_pi = 6.283185307179586;
    double pf = exp(((double)(2*i) / (double)Dn) * log(base));
    double extrap = 1.0 / pf;
    double interp = 1.0 / (16.0 * pf);
    double lowf  = floor((double)Dn * log(8192.0 / (32.0 * two_pi)) / (2.0 * log(base)));
    double highf = ceil ((double)Dn * log(8192.0 / ( 1.0 * two_pi)) / (2.0 * log(base)));
    if (lowf < 0.0) lowf = 0.0;
    if (highf > (double)(Dn-1)) highf = (double)(Dn-1);
    double denom = highf - lowf;
    if (denom < 1.0) denom = 1.0;
    double sm = ((double)i - lowf) / denom;
    sm = fmin(fmax(sm, 0.0), 1.0);
    g_invfreq[i] = (float)((1.0 - sm) * interp + sm * extrap);
}

// ---------------- tf32 GEMM: C[M,N] = A[M,K] @ B[K,N] ----------------
// BM=128, BN=128, BK=32. 256 threads = 8 warps (2x4), warp tile 64x32.
// smem strides: As 36 (=4 mod 32), Bs 132 (=4 mod 32) -> conflict-free frag loads.
#define AS_STR 36
#define BS_STR 132

__global__ __launch_bounds__(256) void gemm_tf32(const float* __restrict__ A,
                                                 const float* __restrict__ Bm,
                                                 float* __restrict__ C,
                                                 int M, int N, int K) {
    __shared__ float As[128*AS_STR];
    __shared__ float Bs[32*BS_STR];
    int tid = threadIdx.x;
    int lane = tid & 31, warp = tid >> 5;
    int wm = warp >> 2, wn = warp & 3;      // warp tile origin: (wm*64, wn*32)
    int bx = blockIdx.x, by = blockIdx.y;

    float acc[4][4][4];
    #pragma unroll
    for (int i = 0; i < 4; i++)
        #pragma unroll
        for (int j = 0; j < 4; j++)
            #pragma unroll
            for (int r = 0; r < 4; r++) acc[i][j][r] = 0.f;

    const int ar  = tid >> 3;           // 0..31? no: 256/8=32 -> rows per pass 32, 4 passes
    const int ac4 = (tid & 7) << 2;     // 0..28
    const int bk  = tid >> 6;           // 0..3 rows per pass (4 passes -> 16? ) see loop
    const int bn4 = (tid & 63) << 1;    // unused; computed in loop

    (void)ar; (void)ac4; (void)bk; (void)bn4;

    for (int kt = 0; kt < K; kt += 32) {
        // prefetch gmem -> regs
        float4 av[4], bv[4];
        #pragma unroll
        for (int l = 0; l < 4; l++) {
            int i = tid + l*256;
            int r = i >> 3, c4 = (i & 7) << 2;
            av[l] = *(const float4*)&A[(size_t)(by*128 + r)*K + kt + c4];
        }
        #pragma unroll
        for (int l = 0; l < 4; l++) {
            int i = tid + l*256;
            int kk = i >> 5, n4 = (i & 31) << 2;
            bv[l] = *(const float4*)&Bm[(size_t)(kt + kk)*N + bx*128 + n4];
        }
        __syncthreads();
        #pragma unroll
        for (int l = 0; l < 4; l++) {
            int i = tid + l*256;
            int r = i >> 3, c4 = (i & 7) << 2;
            *(float4*)&As[r*AS_STR + c4] = make_float4(
                f2tf32f(av[l].x), f2tf32f(av[l].y), f2tf32f(av[l].z), f2tf32f(av[l].w));
        }
        #pragma unroll
        for (int l = 0; l < 4; l++) {
            int i = tid + l*256;
            int kk = i >> 5, n4 = (i & 31) << 2;
            *(float4*)&Bs[kk*BS_STR + n4] = make_float4(
                f2tf32f(bv[l].x), f2tf32f(bv[l].y), f2tf32f(bv[l].z), f2tf32f(bv[l].w));
        }
        __syncthreads();

        #pragma unroll
        for (int ks = 0; ks < 4; ks++) {
            int kcol = ks*8 + (lane & 3);
            unsigned af[4][4];
            #pragma unroll
            for (int mt = 0; mt < 4; mt++) {
                int row = wm*64 + mt*16 + (lane >> 2);
                af[mt][0] = __float_as_uint(As[row*AS_STR + kcol]);
                af[mt][1] = __float_as_uint(As[(row+8)*AS_STR + kcol]);
                af[mt][2] = __float_as_uint(As[row*AS_STR + kcol + 4]);
                af[mt][3] = __float_as_uint(As[(row+8)*AS_STR + kcol + 4]);
            }
            #pragma unroll
            for (int nt = 0; nt < 4; nt++) {
                int col = wn*32 + nt*8 + (lane >> 2);
                unsigned bf[2];
                bf[0] = __float_as_uint(Bs[kcol*BS_STR + col]);
                bf[1] = __float_as_uint(Bs[(kcol+4)*BS_STR + col]);
                #pragma unroll
                for (int mt = 0; mt < 4; mt++)
                    mma_tf32(acc[mt][nt], af[mt], bf);
            }
        }
    }

    // epilogue
    #pragma unroll
    for (int mt = 0; mt < 4; mt++) {
        int row = by*128 + wm*64 + mt*16 + (lane >> 2);
        #pragma unroll
        for (int nt = 0; nt < 4; nt++) {
            int col = bx*128 + wn*32 + nt*8 + 2*(lane & 3);
            *(float2*)&C[(size_t)row*N + col]     = make_float2(acc[mt][nt][0], acc[mt][nt][1]);
            *(float2*)&C[(size_t)(row+8)*N + col] = make_float2(acc[mt][nt][2], acc[mt][nt][3]);
        }
    }
}

// ---------------- RMSNorm ----------------
__global__ __launch_bounds__(128) void rmsnorm_kernel(const float* __restrict__ w) {
    int row = blockIdx.x;
    const float* x = g_kva + (size_t)row * KVAN;
    float* y = g_ckv + (size_t)row * RANKn;
    int tid = threadIdx.x;
    float4 v = *(const float4*)&x[tid*4];
    float ss = v.x*v.x + v.y*v.y + v.z*v.z + v.w*v.w;
    #pragma unroll
    for (int off = 16; off >= 1; off >>= 1)
        ss += __shfl_xor_sync(0xffffffffu, ss, off);
    __shared__ float warp_s[4];
    if ((tid & 31) == 0) warp_s[tid >> 5] = ss;
    __syncthreads();
    float total = warp_s[0] + warp_s[1] + warp_s[2] + warp_s[3];
    float inv = rsqrtf(total * (1.0f/(float)RANKn) + 1e-6f);
    float4 wv = *(const float4*)&w[tid*4];
    *(float4*)&y[tid*4] = make_float4(v.x*wv.x*inv, v.y*wv.y*inv, v.z*wv.z*inv, v.w*wv.w*inv);
}

// ---------------- RoPE q ----------------
__global__ __launch_bounds__(256) void rope_q_kernel(const int* __restrict__ pos_ids) {
    int t = blockIdx.x * 4 + (threadIdx.x >> 6);
    int d = threadIdx.x & 63;
    int bs = t >> 4;
    float p = (float)pos_ids[bs];
    float f = p * g_invfreq[d];
    float sv, cv;
    sincosf(f, &sv, &cv);
    cv *= MSCALE_F; sv *= MSCALE_F;
    float* q = g_q + (size_t)t * Dn;
    float x0 = q[d], x1 = q[d+64];
    q[d]    = x0*cv - x1*sv;
    q[d+64] = x1*cv + x0*sv;
}

// ---------------- RoPE k_rope ----------------
__global__ __launch_bounds__(256) void rope_k_kernel(const int* __restrict__ pos_ids) {
    int bs = blockIdx.x * 4 + (threadIdx.x >> 6);
    int d = threadIdx.x & 63;
    float p = (float)pos_ids[bs];
    float f = p * g_invfreq[d];
    float sv, cv;
    sincosf(f, &sv, &cv);
    cv *= MSCALE_F; sv *= MSCALE_F;
    const float* kr = g_kva + (size_t)bs * KVAN + RANKn;
    float x0 = kr[d], x1 = kr[d+64];
    float* o = g_krope + (size_t)bs * Dn;
    o[d]    = x0*cv - x1*sv;
    o[d+64] = x1*cv + x0*sv;
}

// ---------------- build k,v ----------------
__global__ __launch_bounds__(256) void build_kv_kernel() {
    int idx = blockIdx.x * 256 + threadIdx.x;
    int bs  = idx >> 9;
    int rem = idx & 511;
    int h   = rem >> 5;
    int d4  = (rem & 31) << 2;
    float4 kn = *(const float4*)&g_kv[(size_t)bs*4096 + h*256 + d4];
    float4 vv = *(const float4*)&g_kv[(size_t)bs*4096 + h*256 + 128 + d4];
    float4 kr = *(const float4*)&g_krope[(size_t)bs*128 + d4];
    size_t o = (size_t)bs*HDn + h*Dn + d4;
    *(float4*)&g_k[o] = make_float4(kn.x+kr.x, kn.y+kr.y, kn.z+kr.z, kn.w+kr.w);
    *(float4*)&g_v[o] = vv;
}

// ---------------- tf32 flash attention ----------------
// grid (S/64, B*H), 128 threads = 4 warps; warp w owns q-rows [w*16, w*16+16).
// BM=BN=64, D=128. Qs/Ks/Vs in smem stride 132 (conflict-free frag loads).
#define AT_STR 132
#define FLASH_SMEM_BYTES (3*64*AT_STR*4)

__global__ __launch_bounds__(128) void flash_tf32_kernel() {
    extern __shared__ float smf[];
    float* Qs = smf;
    float* Ks = Qs + 64*AT_STR;
    float* Vs = Ks + 64*AT_STR;

    int tid = threadIdx.x;
    int lane = tid & 31, w = tid >> 5;
    int qt = blockIdx.x;
    int bh = blockIdx.y;
    int b = bh >> 4, h = bh & 15;

    // load Q (scaled, tf32-rounded)
    const float* qbase = g_q + ((size_t)(b*Sn + qt*64)) * HDn + h*Dn;
    #pragma unroll
    for (int l = 0; l < 16; l++) {
        int i = tid + l*128;
        int r = i >> 5, d4 = (i & 31) << 2;
        float4 v = *(const float4*)&qbase[(size_t)r*HDn + d4];
        *(float4*)&Qs[r*AT_STR + d4] = make_float4(
            f2tf32f(v.x*ATTN_SCALE), f2tf32f(v.y*ATTN_SCALE),
            f2tf32f(v.z*ATTN_SCALE), f2tf32f(v.w*ATTN_SCALE));
    }

    const int r0 = w*16 + (lane >> 2);        // local q row (first of the pair)
    float o[16][4];
    float m0 = -1e30f, m1 = -1e30f, l0 = 0.f, l1 = 0.f;
    #pragma unroll
    for (int nt = 0; nt < 16; nt++)
        #pragma unroll
        for (int r = 0; r < 4; r++) o[nt][r] = 0.f;

    const int s1 = (lane & 28) | ((lane >> 1) & 1);
    const int s2 = s1 | 2;
    const bool odd = (lane & 1);

    for (int kt = 0; kt <= qt; kt++) {
        __syncthreads();
        const float* kbase = g_k + ((size_t)(b*Sn + kt*64)) * HDn + h*Dn;
        const float* vbase = g_v + ((size_t)(b*Sn + kt*64)) * HDn + h*Dn;
        #pragma unroll
        for (int l = 0; l < 16; l++) {
            int i = tid + l*128;
            int r = i >> 5, d4 = (i & 31) << 2;
            float4 kv = *(const float4*)&kbase[(size_t)r*HDn + d4];
            *(float4*)&Ks[r*AT_STR + d4] = make_float4(
                f2tf32f(kv.x), f2tf32f(kv.y), f2tf32f(kv.z), f2tf32f(kv.w));
            float4 vv = *(const float4*)&vbase[(size_t)r*HDn + d4];
            *(float4*)&Vs[r*AT_STR + d4] = make_float4(
                f2tf32f(vv.x), f2tf32f(vv.y), f2tf32f(vv.z), f2tf32f(vv.w));
        }
        __syncthreads();

        // S = Q @ K^T  (C-frag layout)
        float sacc[8][4];
        #pragma unroll
        for (int nt = 0; nt < 8; nt++)
            #pragma unroll
            for (int r = 0; r < 4; r++) sacc[nt][r] = 0.f;

        #pragma unroll
        for (int ks = 0; ks < 16; ks++) {
            int kcol = ks*8 + (lane & 3);
            unsigned qa[4];
            qa[0] = __float_as_uint(Qs[r0*AT_STR + kcol]);
            qa[1] = __float_as_uint(Qs[(r0+8)*AT_STR + kcol]);
            qa[2] = __float_as_uint(Qs[r0*AT_STR + kcol + 4]);
            qa[3] = __float_as_uint(Qs[(r0+8)*AT_STR + kcol + 4]);
            #pragma unroll
            for (int nt = 0; nt < 8; nt++) {
                int n = nt*8 + (lane >> 2);
                unsigned bf[2];
                bf[0] = __float_as_uint(Ks[n*AT_STR + kcol]);
                bf[1] = __float_as_uint(Ks[n*AT_STR + kcol + 4]);
                mma_tf32(sacc[nt], qa, bf);
            }
        }

        if (kt == qt) {   // diagonal mask
            #pragma unroll
            for (int nt = 0; nt < 8; nt++) {
                int c = nt*8 + 2*(lane & 3);
                if (c     > r0)   sacc[nt][0] = -1e30f;
                if (c + 1 > r0)   sacc[nt][1] = -1e30f;
                if (c     > r0+8) sacc[nt][2] = -1e30f;
                if (c + 1 > r0+8) sacc[nt][3] = -1e30f;
            }
        }

        // online softmax
        float mx0 = -1e30f, mx1 = -1e30f;
        #pragma unroll
        for (int nt = 0; nt < 8; nt++) {
            mx0 = fmaxf(mx0, fmaxf(sacc[nt][0], sacc[nt][1]));
            mx1 = fmaxf(mx1, fmaxf(sacc[nt][2], sacc[nt][3]));
        }
        mx0 = fmaxf(mx0, __shfl_xor_sync(0xffffffffu, mx0, 1));
        mx0 = fmaxf(mx0, __shfl_xor_sync(0xffffffffu, mx0, 2));
        mx1 = fmaxf(mx1, __shfl_xor_sync(0xffffffffu, mx1, 1));
        mx1 = fmaxf(mx1, __shfl_xor_sync(0xffffffffu, mx1, 2));
        float mn0 = fmaxf(m0, mx0), mn1 = fmaxf(m1, mx1);
        float corr0 = __expf(m0 - mn0), corr1 = __expf(m1 - mn1);
        m0 = mn0; m1 = mn1;

        float sum0 = 0.f, sum1 = 0.f;
        #pragma unroll
        for (int nt = 0; nt < 8; nt++) {
            sacc[nt][0] = __expf(sacc[nt][0] - mn0);
            sacc[nt][1] = __expf(sacc[nt][1] - mn0);
            sacc[nt][2] = __expf(sacc[nt][2] - mn1);
            sacc[nt][3] = __expf(sacc[nt][3] - mn1);
            sum0 += sacc[nt][0] + sacc[nt][1];
            sum1 += sacc[nt][2] + sacc[nt][3];
        }
        sum0 += __shfl_xor_sync(0xffffffffu, sum0, 1);
        sum0 += __shfl_xor_sync(0xffffffffu, sum0, 2);
        sum1 += __shfl_xor_sync(0xffffffffu, sum1, 1);
        sum1 += __shfl_xor_sync(0xffffffffu, sum1, 2);
        l0 = l0*corr0 + sum0;
        l1 = l1*corr1 + sum1;

        #pragma unroll
        for (int nt = 0; nt < 16; nt++) {
            o[nt][0] *= corr0; o[nt][1] *= corr0;
            o[nt][2] *= corr1; o[nt][3] *= corr1;
        }

        // O += P @ V  (P frags via shfl permute from S C-frags)
        #pragma unroll
        for (int kc = 0; kc < 8; kc++) {
            unsigned pa[4];
            float v0, v1;
            v0 = __shfl_sync(0xffffffffu, sacc[kc][0], s1);
            v1 = __shfl_sync(0xffffffffu, sacc[kc][1], s1);
            pa[0] = f2tf32(odd ? v1 : v0);
            v0 = __shfl_sync(0xffffffffu, sacc[kc][2], s1);
            v1 = __shfl_sync(0xffffffffu, sacc[kc][3], s1);
            pa[1] = f2tf32(odd ? v1 : v0);
            v0 = __shfl_sync(0xffffffffu, sacc[kc][0], s2);
            v1 = __shfl_sync(0xffffffffu, sacc[kc][1], s2);
            pa[2] = f2tf32(odd ? v1 : v0);
            v0 = __shfl_sync(0xffffffffu, sacc[kc][2], s2);
            v1 = __shfl_sync(0xffffffffu, sacc[kc][3], s2);
            pa[3] = f2tf32(odd ? v1 : v0);

            int kr = kc*8 + (lane & 3);
            #pragma unroll
            for (int nt = 0; nt < 16; nt++) {
                int d = nt*8 + (lane >> 2);
                unsigned bf[2];
                bf[0] = __float_as_uint(Vs[kr*AT_STR + d]);
                bf[1] = __float_as_uint(Vs[(kr+4)*AT_STR + d]);
                mma_tf32(o[nt], pa, bf);
            }
        }
    }

    // epilogue
    float inv0 = 1.0f / (l0 + 1e-5f);
    float inv1 = 1.0f / (l1 + 1e-5f);
    size_t row0 = (size_t)(b*Sn + qt*64 + r0);
    float* op0 = g_attn + row0*HDn + h*Dn;
    float* op1 = g_attn + (row0+8)*HDn + h*Dn;
    #pragma unroll
    for (int nt = 0; nt < 16; nt++) {
        int d = nt*8 + 2*(lane & 3);
        *(float2*)&op0[d] = make_float2(o[nt][0]*inv0, o[nt][1]*inv0);
        *(float2*)&op1[d] = make_float2(o[nt][2]*inv1, o[nt][3]*inv1);
    }
}

// ---------------- launch ----------------
extern "C" void kernel_launch(void* const* d_in, const int* in_sizes, int n_in,
                              void* d_out, int out_size) {
    const float* hidden  = (const float*)d_in[0];
    const int*   pos_ids = (const int*)  d_in[1];
    const float* w_q     = (const float*)d_in[2];
    const float* w_kv_a  = (const float*)d_in[3];
    const float* w_kv_b  = (const float*)d_in[4];
    const float* w_o     = (const float*)d_in[5];
    const float* kv_ln_w = (const float*)d_in[6];
    float* out = (float*)d_out;

    float *pq, *pkva, *pckv, *pkv, *pattn;
    cudaGetSymbolAddress((void**)&pq,    g_q);
    cudaGetSymbolAddress((void**)&pkva,  g_kva);
    cudaGetSymbolAddress((void**)&pckv,  g_ckv);
    cudaGetSymbolAddress((void**)&pkv,   g_kv);
    cudaGetSymbolAddress((void**)&pattn, g_attn);

    cudaFuncSetAttribute(flash_tf32_kernel, cudaFuncAttributeMaxDynamicSharedMemorySize,
                         FLASH_SMEM_BYTES);

    init_invfreq_kernel<<<1, 64>>>();

    // q = hidden @ w_q : [4096, 2048]
    gemm_tf32<<<dim3(HDn/128, BSn/128), 256>>>(hidden, w_q, pq, BSn, HDn, HIDn);
    // kv_a = hidden @ w_kv_a : [4096, 640]
    gemm_tf32<<<dim3(KVAN/128, BSn/128), 256>>>(hidden, w_kv_a, pkva, BSn, KVAN, HIDn);

    rmsnorm_kernel<<<BSn, 128>>>(kv_ln_w);
    rope_k_kernel<<<BSn/4, 256>>>(pos_ids);

    // kv = ckv @ w_kv_b : [4096, 4096]
    gemm_tf32<<<dim3((Hn*2*Dn)/128, BSn/128), 256>>>(pckv, w_kv_b, pkv, BSn, Hn*2*Dn, RANKn);

    rope_q_kernel<<<(BSn*Hn)/4, 256>>>(pos_ids);
    build_kv_kernel<<<(BSn*HDn/4)/256, 256>>>();

    flash_tf32_kernel<<<dim3(Sn/64, Bn*Hn), 128, FLASH_SMEM_BYTES>>>();

    // out = attn @ w_o : [4096, 2048]
    gemm_tf32<<<dim3(HIDn/128, BSn/128), 256>>>(pattn, w_o, out, BSn, HIDn, HIDn);
}

// round 5
// speedup vs baseline: 3.2605x; 1.1283x over previous
#include <cuda_runtime.h>
#include <math.h>

// ---------------- problem constants ----------------
#define Bn    2
#define Sn    2048
#define HIDn  2048
#define Hn    16
#define Dn    128
#define RANKn 512
#define BSn   (Bn*Sn)        // 4096
#define KVAN  (RANKn+Dn)     // 640
#define HDn   (Hn*Dn)        // 2048

#define MSCALE_F    1.2772588722239781f
#define ATTN_SCALE  0.08838834764831845f

// ---------------- scratch ----------------
__device__ float g_q[(size_t)BSn*HDn];        // q proj -> rope'd+scaled+rounded
__device__ float g_kva[(size_t)BSn*KVAN];     // kv_a proj (raw)
__device__ float g_ckv[(size_t)BSn*RANKn];    // rmsnormed, rounded
__device__ float g_kv[(size_t)BSn*Hn*2*Dn];   // kv_b proj, rounded
__device__ float g_krope[(size_t)BSn*Dn];     // rope'd shared k_rope (raw)
__device__ float g_attn[(size_t)BSn*HDn];     // attention out, rounded
__device__ float g_invfreq[Dn/2];
// pre-rounded (tf32-in-f32) copies of inputs
__device__ float g_hid_r[(size_t)BSn*HIDn];
__device__ float g_wq_r[(size_t)HIDn*HDn];
__device__ float g_wkva_r[(size_t)HIDn*KVAN];
__device__ float g_wkvb_r[(size_t)RANKn*Hn*2*Dn];
__device__ float g_wo_r[(size_t)HDn*HIDn];

// ---------------- tf32 helpers ----------------
__device__ __forceinline__ unsigned f2tf32(float x) {
    unsigned u;
    asm("cvt.rna.tf32.f32 %0, %1;" : "=r"(u) : "f"(x));
    return u;
}
__device__ __forceinline__ float f2tf32f(float x) { return __uint_as_float(f2tf32(x)); }

__device__ __forceinline__ void mma_tf32(float* c, const unsigned* a, const unsigned* b) {
    asm volatile(
        "mma.sync.aligned.m16n8k8.row.col.f32.tf32.tf32.f32 "
        "{%0,%1,%2,%3}, {%4,%5,%6,%7}, {%8,%9}, {%0,%1,%2,%3};"
        : "+f"(c[0]), "+f"(c[1]), "+f"(c[2]), "+f"(c[3])
        : "r"(a[0]), "r"(a[1]), "r"(a[2]), "r"(a[3]), "r"(b[0]), "r"(b[1]));
}

__device__ __forceinline__ void cp16(float* smem_dst, const float* gmem_src) {
    unsigned d = (unsigned)__cvta_generic_to_shared(smem_dst);
    asm volatile("cp.async.cg.shared.global [%0], [%1], 16;" :: "r"(d), "l"(gmem_src));
}
__device__ __forceinline__ void cp_commit() { asm volatile("cp.async.commit_group;"); }
__device__ __forceinline__ void cp_wait0()  { asm volatile("cp.async.wait_group 0;"); }

// ---------------- pre-round inputs ----------------
__global__ __launch_bounds__(256) void round_copy_kernel(const float* __restrict__ src,
                                                         float* __restrict__ dst, int n4) {
    int i = blockIdx.x * 256 + threadIdx.x;
    if (i >= n4) return;
    float4 v = ((const float4*)src)[i];
    ((float4*)dst)[i] = make_float4(f2tf32f(v.x), f2tf32f(v.y), f2tf32f(v.z), f2tf32f(v.w));
}

// ---------------- YaRN inv_freq ----------------
__global__ void init_invfreq_kernel() {
    int i = threadIdx.x;
    if (i >= Dn/2) return;
    const double base = 500000.0;
    const double two_pi = 6.283185307179586;
    double pf = exp(((double)(2*i) / (double)Dn) * log(base));
    double extrap = 1.0 / pf;
    double interp = 1.0 / (16.0 * pf);
    double lowf  = floor((double)Dn * log(8192.0 / (32.0 * two_pi)) / (2.0 * log(base)));
    double highf = ceil ((double)Dn * log(8192.0 / ( 1.0 * two_pi)) / (2.0 * log(base)));
    if (lowf < 0.0) lowf = 0.0;
    if (highf > (double)(Dn-1)) highf = (double)(Dn-1);
    double denom = highf - lowf;
    if (denom < 1.0) denom = 1.0;
    double sm = ((double)i - lowf) / denom;
    sm = fmin(fmax(sm, 0.0), 1.0);
    g_invfreq[i] = (float)((1.0 - sm) * interp + sm * extrap);
}

// ---------------- tf32 GEMM, cp.async 2-stage ----------------
// BM=128, BN=128, BK=32, 256 threads (8 warps 2x4, warp tile 64x32).
// Inputs must already be tf32-rounded. roundC: round outputs.
#define AS_STR 36
#define BS_STR 132
#define A_STAGE (128*AS_STR)
#define B_STAGE (32*BS_STR)
#define GEMM_SMEM_BYTES ((2*A_STAGE + 2*B_STAGE)*4)

__global__ __launch_bounds__(256) void gemm_tf32(const float* __restrict__ A,
                                                 const float* __restrict__ Bm,
                                                 float* __restrict__ C,
                                                 int M, int N, int K, int roundC) {
    extern __shared__ float sm[];
    float* As = sm;                    // [2][128*36]
    float* Bs = sm + 2*A_STAGE;        // [2][32*132]

    int tid = threadIdx.x;
    int lane = tid & 31, warp = tid >> 5;
    int wm = warp >> 2, wn = warp & 3;
    int bx = blockIdx.x, by = blockIdx.y;

    const int ar = tid >> 3, ac4 = (tid & 7) << 2;     // A: 32 rows/pass x4
    const int bk = tid >> 5, bn4 = (tid & 31) << 2;    // B: 8 rows/pass x4

    const float* Abase = A + (size_t)(by*128)*K;
    const float* Bbase = Bm + (size_t)bx*128;

    float acc[4][4][4];
    #pragma unroll
    for (int i = 0; i < 4; i++)
        #pragma unroll
        for (int j = 0; j < 4; j++)
            #pragma unroll
            for (int r = 0; r < 4; r++) acc[i][j][r] = 0.f;

    int T = K >> 5;

    // prologue: stage 0
    {
        float* Ad = As;  float* Bd = Bs;
        #pragma unroll
        for (int l = 0; l < 4; l++)
            cp16(&Ad[(ar + l*32)*AS_STR + ac4], &Abase[(size_t)(ar + l*32)*K + ac4]);
        #pragma unroll
        for (int l = 0; l < 4; l++)
            cp16(&Bd[(bk + l*8)*BS_STR + bn4], &Bbase[(size_t)(bk + l*8)*N + bn4]);
        cp_commit();
    }

    for (int t = 0; t < T; t++) {
        cp_wait0();
        __syncthreads();
        int st = t & 1;
        if (t + 1 < T) {
            int kt = (t + 1) << 5;
            float* Ad = As + (st ^ 1)*A_STAGE;
            float* Bd = Bs + (st ^ 1)*B_STAGE;
            #pragma unroll
            for (int l = 0; l < 4; l++)
                cp16(&Ad[(ar + l*32)*AS_STR + ac4], &Abase[(size_t)(ar + l*32)*K + kt + ac4]);
            #pragma unroll
            for (int l = 0; l < 4; l++)
                cp16(&Bd[(bk + l*8)*BS_STR + bn4], &Bbase[(size_t)(kt + bk + l*8)*N + bn4]);
            cp_commit();
        }
        const float* As_ = As + st*A_STAGE;
        const float* Bs_ = Bs + st*B_STAGE;
        #pragma unroll
        for (int ks = 0; ks < 4; ks++) {
            int kcol = ks*8 + (lane & 3);
            unsigned af[4][4];
            #pragma unroll
            for (int mt = 0; mt < 4; mt++) {
                int row = wm*64 + mt*16 + (lane >> 2);
                af[mt][0] = __float_as_uint(As_[row*AS_STR + kcol]);
                af[mt][1] = __float_as_uint(As_[(row+8)*AS_STR + kcol]);
                af[mt][2] = __float_as_uint(As_[row*AS_STR + kcol + 4]);
                af[mt][3] = __float_as_uint(As_[(row+8)*AS_STR + kcol + 4]);
            }
            #pragma unroll
            for (int nt = 0; nt < 4; nt++) {
                int col = wn*32 + nt*8 + (lane >> 2);
                unsigned bf[2];
                bf[0] = __float_as_uint(Bs_[kcol*BS_STR + col]);
                bf[1] = __float_as_uint(Bs_[(kcol+4)*BS_STR + col]);
                #pragma unroll
                for (int mt = 0; mt < 4; mt++)
                    mma_tf32(acc[mt][nt], af[mt], bf);
            }
        }
        __syncthreads();
    }

    #pragma unroll
    for (int mt = 0; mt < 4; mt++) {
        int row = by*128 + wm*64 + mt*16 + (lane >> 2);
        #pragma unroll
        for (int nt = 0; nt < 4; nt++) {
            int col = bx*128 + wn*32 + nt*8 + 2*(lane & 3);
            float v0 = acc[mt][nt][0], v1 = acc[mt][nt][1];
            float v2 = acc[mt][nt][2], v3 = acc[mt][nt][3];
            if (roundC) { v0 = f2tf32f(v0); v1 = f2tf32f(v1); v2 = f2tf32f(v2); v3 = f2tf32f(v3); }
            *(float2*)&C[(size_t)row*N + col]     = make_float2(v0, v1);
            *(float2*)&C[(size_t)(row+8)*N + col] = make_float2(v2, v3);
        }
    }
}

// ---------------- RMSNorm (rounds output) ----------------
__global__ __launch_bounds__(128) void rmsnorm_kernel(const float* __restrict__ w) {
    int row = blockIdx.x;
    const float* x = g_kva + (size_t)row * KVAN;
    float* y = g_ckv + (size_t)row * RANKn;
    int tid = threadIdx.x;
    float4 v = *(const float4*)&x[tid*4];
    float ss = v.x*v.x + v.y*v.y + v.z*v.z + v.w*v.w;
    #pragma unroll
    for (int off = 16; off >= 1; off >>= 1)
        ss += __shfl_xor_sync(0xffffffffu, ss, off);
    __shared__ float warp_s[4];
    if ((tid & 31) == 0) warp_s[tid >> 5] = ss;
    __syncthreads();
    float total = warp_s[0] + warp_s[1] + warp_s[2] + warp_s[3];
    float inv = rsqrtf(total * (1.0f/(float)RANKn) + 1e-6f);
    float4 wv = *(const float4*)&w[tid*4];
    *(float4*)&y[tid*4] = make_float4(f2tf32f(v.x*wv.x*inv), f2tf32f(v.y*wv.y*inv),
                                      f2tf32f(v.z*wv.z*inv), f2tf32f(v.w*wv.w*inv));
}

// ---------------- RoPE q (in place): rotate, *ATTN_SCALE, round ----------------
__global__ __launch_bounds__(256) void rope_q_kernel(const int* __restrict__ pos_ids) {
    int t = blockIdx.x * 4 + (threadIdx.x >> 6);
    int d = threadIdx.x & 63;
    int bs = t >> 4;
    float p = (float)pos_ids[bs];
    float f = p * g_invfreq[d];
    float sv, cv;
    sincosf(f, &sv, &cv);
    cv *= MSCALE_F; sv *= MSCALE_F;
    float* q = g_q + (size_t)t * Dn;
    float x0 = q[d], x1 = q[d+64];
    q[d]    = f2tf32f((x0*cv - x1*sv) * ATTN_SCALE);
    q[d+64] = f2tf32f((x1*cv + x0*sv) * ATTN_SCALE);
}

// ---------------- RoPE k_rope (raw out; rounded at flash fill) ----------------
__global__ __launch_bounds__(256) void rope_k_kernel(const int* __restrict__ pos_ids) {
    int bs = blockIdx.x * 4 + (threadIdx.x >> 6);
    int d = threadIdx.x & 63;
    float p = (float)pos_ids[bs];
    float f = p * g_invfreq[d];
    float sv, cv;
    sincosf(f, &sv, &cv);
    cv *= MSCALE_F; sv *= MSCALE_F;
    const float* kr = g_kva + (size_t)bs * KVAN + RANKn;
    float x0 = kr[d], x1 = kr[d+64];
    float* o = g_krope + (size_t)bs * Dn;
    o[d]    = x0*cv - x1*sv;
    o[d+64] = x1*cv + x0*sv;
}

// ---------------- tf32 flash attention, Q register-resident ----------------
// grid (S/64, B*H), 128 threads = 4 warps; warp w owns q-rows [w*16, w*16+16).
#define AT_STR 132
#define FLASH_SMEM_BYTES (2*64*AT_STR*4)

__global__ __launch_bounds__(128) void flash_tf32_kernel() {
    extern __shared__ float smf[];
    float* Ks = smf;
    float* Vs = Ks + 64*AT_STR;

    int tid = threadIdx.x;
    int lane = tid & 31, w = tid >> 5;
    int qt = blockIdx.x;
    int bh = blockIdx.y;
    int b = bh >> 4, h = bh & 15;

    const int r0 = w*16 + (lane >> 2);

    // stage Q through Ks, then pull fragments into registers (g_q already scaled+rounded)
    const float* qbase = g_q + ((size_t)(b*Sn + qt*64)) * HDn + h*Dn;
    #pragma unroll
    for (int l = 0; l < 16; l++) {
        int i = tid + l*128;
        int r = i >> 5, d4 = (i & 31) << 2;
        *(float4*)&Ks[r*AT_STR + d4] = *(const float4*)&qbase[(size_t)r*HDn + d4];
    }
    __syncthreads();
    unsigned qf[16][4];
    #pragma unroll
    for (int ks = 0; ks < 16; ks++) {
        int kcol = ks*8 + (lane & 3);
        qf[ks][0] = __float_as_uint(Ks[r0*AT_STR + kcol]);
        qf[ks][1] = __float_as_uint(Ks[(r0+8)*AT_STR + kcol]);
        qf[ks][2] = __float_as_uint(Ks[r0*AT_STR + kcol + 4]);
        qf[ks][3] = __float_as_uint(Ks[(r0+8)*AT_STR + kcol + 4]);
    }

    float o[16][4];
    float m0 = -1e30f, m1 = -1e30f, l0 = 0.f, l1 = 0.f;
    #pragma unroll
    for (int nt = 0; nt < 16; nt++)
        #pragma unroll
        for (int r = 0; r < 4; r++) o[nt][r] = 0.f;

    const int s1 = (lane & 28) | ((lane >> 1) & 1);
    const int s2 = s1 | 2;
    const bool odd = (lane & 1);

    for (int kt = 0; kt <= qt; kt++) {
        __syncthreads();
        // fill K (= kv_nope + krope, rounded) and V (already rounded) from g_kv/g_krope
        size_t tok0 = (size_t)(b*Sn + kt*64);
        #pragma unroll
        for (int l = 0; l < 16; l++) {
            int i = tid + l*128;
            int r = i >> 5, d4 = (i & 31) << 2;
            size_t base = (tok0 + r)*((size_t)Hn*2*Dn) + h*256;
            float4 kn = *(const float4*)&g_kv[base + d4];
            float4 kr = *(const float4*)&g_krope[(tok0 + r)*Dn + d4];
            *(float4*)&Ks[r*AT_STR + d4] = make_float4(
                f2tf32f(kn.x + kr.x), f2tf32f(kn.y + kr.y),
                f2tf32f(kn.z + kr.z), f2tf32f(kn.w + kr.w));
            *(float4*)&Vs[r*AT_STR + d4] = *(const float4*)&g_kv[base + 128 + d4];
        }
        __syncthreads();

        // S = Q @ K^T
        float sacc[8][4];
        #pragma unroll
        for (int nt = 0; nt < 8; nt++)
            #pragma unroll
            for (int r = 0; r < 4; r++) sacc[nt][r] = 0.f;

        #pragma unroll
        for (int ks = 0; ks < 16; ks++) {
            int kcol = ks*8 + (lane & 3);
            #pragma unroll
            for (int nt = 0; nt < 8; nt++) {
                int n = nt*8 + (lane >> 2);
                unsigned bf[2];
                bf[0] = __float_as_uint(Ks[n*AT_STR + kcol]);
                bf[1] = __float_as_uint(Ks[n*AT_STR + kcol + 4]);
                mma_tf32(sacc[nt], qf[ks], bf);
            }
        }

        if (kt == qt) {
            #pragma unroll
            for (int nt = 0; nt < 8; nt++) {
                int c = nt*8 + 2*(lane & 3);
                if (c     > r0)   sacc[nt][0] = -1e30f;
                if (c + 1 > r0)   sacc[nt][1] = -1e30f;
                if (c     > r0+8) sacc[nt][2] = -1e30f;
                if (c + 1 > r0+8) sacc[nt][3] = -1e30f;
            }
        }

        // online softmax
        float mx0 = -1e30f, mx1 = -1e30f;
        #pragma unroll
        for (int nt = 0; nt < 8; nt++) {
            mx0 = fmaxf(mx0, fmaxf(sacc[nt][0], sacc[nt][1]));
            mx1 = fmaxf(mx1, fmaxf(sacc[nt][2], sacc[nt][3]));
        }
        mx0 = fmaxf(mx0, __shfl_xor_sync(0xffffffffu, mx0, 1));
        mx0 = fmaxf(mx0, __shfl_xor_sync(0xffffffffu, mx0, 2));
        mx1 = fmaxf(mx1, __shfl_xor_sync(0xffffffffu, mx1, 1));
        mx1 = fmaxf(mx1, __shfl_xor_sync(0xffffffffu, mx1, 2));
        float mn0 = fmaxf(m0, mx0), mn1 = fmaxf(m1, mx1);
        float corr0 = __expf(m0 - mn0), corr1 = __expf(m1 - mn1);
        m0 = mn0; m1 = mn1;

        float sum0 = 0.f, sum1 = 0.f;
        #pragma unroll
        for (int nt = 0; nt < 8; nt++) {
            sacc[nt][0] = __expf(sacc[nt][0] - mn0);
            sacc[nt][1] = __expf(sacc[nt][1] - mn0);
            sacc[nt][2] = __expf(sacc[nt][2] - mn1);
            sacc[nt][3] = __expf(sacc[nt][3] - mn1);
            sum0 += sacc[nt][0] + sacc[nt][1];
            sum1 += sacc[nt][2] + sacc[nt][3];
        }
        sum0 += __shfl_xor_sync(0xffffffffu, sum0, 1);
        sum0 += __shfl_xor_sync(0xffffffffu, sum0, 2);
        sum1 += __shfl_xor_sync(0xffffffffu, sum1, 1);
        sum1 += __shfl_xor_sync(0xffffffffu, sum1, 2);
        l0 = l0*corr0 + sum0;
        l1 = l1*corr1 + sum1;

        #pragma unroll
        for (int nt = 0; nt < 16; nt++) {
            o[nt][0] *= corr0; o[nt][1] *= corr0;
            o[nt][2] *= corr1; o[nt][3] *= corr1;
        }

        // O += P @ V
        #pragma unroll
        for (int kc = 0; kc < 8; kc++) {
            unsigned pa[4];
            float v0, v1;
            v0 = __shfl_sync(0xffffffffu, sacc[kc][0], s1);
            v1 = __shfl_sync(0xffffffffu, sacc[kc][1], s1);
            pa[0] = f2tf32(odd ? v1 : v0);
            v0 = __shfl_sync(0xffffffffu, sacc[kc][2], s1);
            v1 = __shfl_sync(0xffffffffu, sacc[kc][3], s1);
            pa[1] = f2tf32(odd ? v1 : v0);
            v0 = __shfl_sync(0xffffffffu, sacc[kc][0], s2);
            v1 = __shfl_sync(0xffffffffu, sacc[kc][1], s2);
            pa[2] = f2tf32(odd ? v1 : v0);
            v0 = __shfl_sync(0xffffffffu, sacc[kc][2], s2);
            v1 = __shfl_sync(0xffffffffu, sacc[kc][3], s2);
            pa[3] = f2tf32(odd ? v1 : v0);

            int kr = kc*8 + (lane & 3);
            #pragma unroll
            for (int nt = 0; nt < 16; nt++) {
                int d = nt*8 + (lane >> 2);
                unsigned bf[2];
                bf[0] = __float_as_uint(Vs[kr*AT_STR + d]);
                bf[1] = __float_as_uint(Vs[(kr+4)*AT_STR + d]);
                mma_tf32(o[nt], pa, bf);
            }
        }
    }

    // epilogue (rounded: feeds tf32 o-proj GEMM)
    float inv0 = 1.0f / (l0 + 1e-5f);
    float inv1 = 1.0f / (l1 + 1e-5f);
    size_t row0 = (size_t)(b*Sn + qt*64 + r0);
    float* op0 = g_attn + row0*HDn + h*Dn;
    float* op1 = g_attn + (row0+8)*HDn + h*Dn;
    #pragma unroll
    for (int nt = 0; nt < 16; nt++) {
        int d = nt*8 + 2*(lane & 3);
        *(float2*)&op0[d] = make_float2(f2tf32f(o[nt][0]*inv0), f2tf32f(o[nt][1]*inv0));
        *(float2*)&op1[d] = make_float2(f2tf32f(o[nt][2]*inv1), f2tf32f(o[nt][3]*inv1));
    }
}

// ---------------- launch ----------------
extern "C" void kernel_launch(void* const* d_in, const int* in_sizes, int n_in,
                              void* d_out, int out_size) {
    const float* hidden  = (const float*)d_in[0];
    const int*   pos_ids = (const int*)  d_in[1];
    const float* w_q     = (const float*)d_in[2];
    const float* w_kv_a  = (const float*)d_in[3];
    const float* w_kv_b  = (const float*)d_in[4];
    const float* w_o     = (const float*)d_in[5];
    const float* kv_ln_w = (const float*)d_in[6];
    float* out = (float*)d_out;

    float *pq, *pckv, *pkv, *pattn;
    float *phid, *pwq, *pwkva, *pwkvb, *pwo;
    cudaGetSymbolAddress((void**)&pq,    g_q);
    cudaGetSymbolAddress((void**)&pckv,  g_ckv);
    cudaGetSymbolAddress((void**)&pkv,   g_kv);
    cudaGetSymbolAddress((void**)&pattn, g_attn);
    cudaGetSymbolAddress((void**)&phid,  g_hid_r);
    cudaGetSymbolAddress((void**)&pwq,   g_wq_r);
    cudaGetSymbolAddress((void**)&pwkva, g_wkva_r);
    cudaGetSymbolAddress((void**)&pwkvb, g_wkvb_r);
    cudaGetSymbolAddress((void**)&pwo,   g_wo_r);
    float* pkva;
    cudaGetSymbolAddress((void**)&pkva,  g_kva);

    cudaFuncSetAttribute(flash_tf32_kernel, cudaFuncAttributeMaxDynamicSharedMemorySize,
                         FLASH_SMEM_BYTES);
    cudaFuncSetAttribute(gemm_tf32, cudaFuncAttributeMaxDynamicSharedMemorySize,
                         GEMM_SMEM_BYTES);

    init_invfreq_kernel<<<1, 64>>>();

    // pre-round inputs to tf32 (eliminates all in-loop cvt)
    round_copy_kernel<<<(BSn*HIDn/4 + 255)/256, 256>>>(hidden, phid, BSn*HIDn/4);
    round_copy_kernel<<<(HIDn*HDn/4 + 255)/256, 256>>>(w_q, pwq, HIDn*HDn/4);
    round_copy_kernel<<<(HIDn*KVAN/4 + 255)/256, 256>>>(w_kv_a, pwkva, HIDn*KVAN/4);
    round_copy_kernel<<<(RANKn*Hn*2*Dn/4 + 255)/256, 256>>>(w_kv_b, pwkvb, RANKn*Hn*2*Dn/4);
    round_copy_kernel<<<(HDn*HIDn/4 + 255)/256, 256>>>(w_o, pwo, HDn*HIDn/4);

    // q = hidden @ w_q
    gemm_tf32<<<dim3(HDn/128, BSn/128), 256, GEMM_SMEM_BYTES>>>(phid, pwq, pq, BSn, HDn, HIDn, 0);
    // kv_a = hidden @ w_kv_a
    gemm_tf32<<<dim3(KVAN/128, BSn/128), 256, GEMM_SMEM_BYTES>>>(phid, pwkva, pkva, BSn, KVAN, HIDn, 0);

    rmsnorm_kernel<<<BSn, 128>>>(kv_ln_w);
    rope_k_kernel<<<BSn/4, 256>>>(pos_ids);

    // kv = ckv @ w_kv_b (rounded output: feeds attention)
    gemm_tf32<<<dim3((Hn*2*Dn)/128, BSn/128), 256, GEMM_SMEM_BYTES>>>(pckv, pwkvb, pkv, BSn, Hn*2*Dn, RANKn, 1);

    rope_q_kernel<<<(BSn*Hn)/4, 256>>>(pos_ids);

    flash_tf32_kernel<<<dim3(Sn/64, Bn*Hn), 128, FLASH_SMEM_BYTES>>>();

    // out = attn @ w_o (raw fp32 output)
    gemm_tf32<<<dim3(HIDn/128, BSn/128), 256, GEMM_SMEM_BYTES>>>(pattn, pwo, out, BSn, HIDn, HIDn, 0);
}

// round 6
// speedup vs baseline: 3.2699x; 1.0029x over previous
#include <cuda_runtime.h>
#include <math.h>

// ---------------- problem constants ----------------
#define Bn    2
#define Sn    2048
#define HIDn  2048
#define Hn    16
#define Dn    128
#define RANKn 512
#define BSn   (Bn*Sn)        // 4096
#define KVAN  (RANKn+Dn)     // 640
#define HDn   (Hn*Dn)        // 2048

#define MSCALE_F    1.2772588722239781f
#define ATTN_SCALE  0.08838834764831845f

// ---------------- scratch ----------------
__device__ float g_q[(size_t)BSn*HDn];        // q proj -> rope'd+scaled+rounded
__device__ float g_kva[(size_t)BSn*KVAN];     // kv_a proj (raw)
__device__ float g_ckv[(size_t)BSn*RANKn];    // rmsnormed, rounded
__device__ float g_kv[(size_t)BSn*Hn*2*Dn];   // kv_b proj, rounded
__device__ float g_krope[(size_t)BSn*Dn];     // rope'd shared k_rope (raw)
__device__ float g_attn[(size_t)BSn*HDn];     // attention out, rounded
__device__ float g_invfreq[Dn/2];
// pre-rounded (tf32-in-f32) copies of inputs
__device__ float g_hid_r[(size_t)BSn*HIDn];
__device__ float g_wq_r[(size_t)HIDn*HDn];
__device__ float g_wkva_r[(size_t)HIDn*KVAN];
__device__ float g_wkvb_r[(size_t)RANKn*Hn*2*Dn];
__device__ float g_wo_r[(size_t)HDn*HIDn];

// ---------------- tf32 helpers ----------------
__device__ __forceinline__ unsigned f2tf32(float x) {
    unsigned u;
    asm("cvt.rna.tf32.f32 %0, %1;" : "=r"(u) : "f"(x));
    return u;
}
__device__ __forceinline__ float f2tf32f(float x) { return __uint_as_float(f2tf32(x)); }

__device__ __forceinline__ void mma_tf32(float* c, const unsigned* a, const unsigned* b) {
    asm volatile(
        "mma.sync.aligned.m16n8k8.row.col.f32.tf32.tf32.f32 "
        "{%0,%1,%2,%3}, {%4,%5,%6,%7}, {%8,%9}, {%0,%1,%2,%3};"
        : "+f"(c[0]), "+f"(c[1]), "+f"(c[2]), "+f"(c[3])
        : "r"(a[0]), "r"(a[1]), "r"(a[2]), "r"(a[3]), "r"(b[0]), "r"(b[1]));
}

__device__ __forceinline__ void cp16(float* smem_dst, const float* gmem_src) {
    unsigned d = (unsigned)__cvta_generic_to_shared(smem_dst);
    asm volatile("cp.async.cg.shared.global [%0], [%1], 16;" :: "r"(d), "l"(gmem_src));
}
__device__ __forceinline__ void cp_commit() { asm volatile("cp.async.commit_group;"); }
__device__ __forceinline__ void cp_wait0()  { asm volatile("cp.async.wait_group 0;"); }

// ---------------- pre-round inputs ----------------
__global__ __launch_bounds__(256) void round_copy_kernel(const float* __restrict__ src,
                                                         float* __restrict__ dst, int n4) {
    int i = blockIdx.x * 256 + threadIdx.x;
    if (i >= n4) return;
    float4 v = ((const float4*)src)[i];
    ((float4*)dst)[i] = make_float4(f2tf32f(v.x), f2tf32f(v.y), f2tf32f(v.z), f2tf32f(v.w));
}

// ---------------- YaRN inv_freq ----------------
__global__ void init_invfreq_kernel() {
    int i = threadIdx.x;
    if (i >= Dn/2) return;
    const double base = 500000.0;
    const double two_pi = 6.283185307179586;
    double pf = exp(((double)(2*i) / (double)Dn) * log(base));
    double extrap = 1.0 / pf;
    double interp = 1.0 / (16.0 * pf);
    double lowf  = floor((double)Dn * log(8192.0 / (32.0 * two_pi)) / (2.0 * log(base)));
    double highf = ceil ((double)Dn * log(8192.0 / ( 1.0 * two_pi)) / (2.0 * log(base)));
    if (lowf < 0.0) lowf = 0.0;
    if (highf > (double)(Dn-1)) highf = (double)(Dn-1);
    double denom = highf - lowf;
    if (denom < 1.0) denom = 1.0;
    double sm = ((double)i - lowf) / denom;
    sm = fmin(fmax(sm, 0.0), 1.0);
    g_invfreq[i] = (float)((1.0 - sm) * interp + sm * extrap);
}

// ---------------- tf32 GEMM, cp.async 2-stage ----------------
// BM=128, BN=128, BK=32, 256 threads (8 warps 2x4, warp tile 64x32).
// Inputs must already be tf32-rounded. roundC: round outputs.
#define AS_STR 36
#define BS_STR 132
#define A_STAGE (128*AS_STR)
#define B_STAGE (32*BS_STR)
#define GEMM_SMEM_BYTES ((2*A_STAGE + 2*B_STAGE)*4)

__global__ __launch_bounds__(256) void gemm_tf32(const float* __restrict__ A,
                                                 const float* __restrict__ Bm,
                                                 float* __restrict__ C,
                                                 int M, int N, int K, int roundC) {
    extern __shared__ float sm[];
    float* As = sm;                    // [2][128*36]
    float* Bs = sm + 2*A_STAGE;        // [2][32*132]

    int tid = threadIdx.x;
    int lane = tid & 31, warp = tid >> 5;
    int wm = warp >> 2, wn = warp & 3;
    int bx = blockIdx.x, by = blockIdx.y;

    const int ar = tid >> 3, ac4 = (tid & 7) << 2;     // A: 32 rows/pass x4
    const int bk = tid >> 5, bn4 = (tid & 31) << 2;    // B: 8 rows/pass x4

    const float* Abase = A + (size_t)(by*128)*K;
    const float* Bbase = Bm + (size_t)bx*128;

    float acc[4][4][4];
    #pragma unroll
    for (int i = 0; i < 4; i++)
        #pragma unroll
        for (int j = 0; j < 4; j++)
            #pragma unroll
            for (int r = 0; r < 4; r++) acc[i][j][r] = 0.f;

    int T = K >> 5;

    // prologue: stage 0
    {
        float* Ad = As;  float* Bd = Bs;
        #pragma unroll
        for (int l = 0; l < 4; l++)
            cp16(&Ad[(ar + l*32)*AS_STR + ac4], &Abase[(size_t)(ar + l*32)*K + ac4]);
        #pragma unroll
        for (int l = 0; l < 4; l++)
            cp16(&Bd[(bk + l*8)*BS_STR + bn4], &Bbase[(size_t)(bk + l*8)*N + bn4]);
        cp_commit();
    }

    for (int t = 0; t < T; t++) {
        cp_wait0();
        __syncthreads();
        int st = t & 1;
        if (t + 1 < T) {
            int kt = (t + 1) << 5;
            float* Ad = As + (st ^ 1)*A_STAGE;
            float* Bd = Bs + (st ^ 1)*B_STAGE;
            #pragma unroll
            for (int l = 0; l < 4; l++)
                cp16(&Ad[(ar + l*32)*AS_STR + ac4], &Abase[(size_t)(ar + l*32)*K + kt + ac4]);
            #pragma unroll
            for (int l = 0; l < 4; l++)
                cp16(&Bd[(bk + l*8)*BS_STR + bn4], &Bbase[(size_t)(kt + bk + l*8)*N + bn4]);
            cp_commit();
        }
        const float* As_ = As + st*A_STAGE;
        const float* Bs_ = Bs + st*B_STAGE;
        #pragma unroll
        for (int ks = 0; ks < 4; ks++) {
            int kcol = ks*8 + (lane & 3);
            unsigned af[4][4];
            #pragma unroll
            for (int mt = 0; mt < 4; mt++) {
                int row = wm*64 + mt*16 + (lane >> 2);
                af[mt][0] = __float_as_uint(As_[row*AS_STR + kcol]);
                af[mt][1] = __float_as_uint(As_[(row+8)*AS_STR + kcol]);
                af[mt][2] = __float_as_uint(As_[row*AS_STR + kcol + 4]);
                af[mt][3] = __float_as_uint(As_[(row+8)*AS_STR + kcol + 4]);
            }
            #pragma unroll
            for (int nt = 0; nt < 4; nt++) {
                int col = wn*32 + nt*8 + (lane >> 2);
                unsigned bf[2];
                bf[0] = __float_as_uint(Bs_[kcol*BS_STR + col]);
                bf[1] = __float_as_uint(Bs_[(kcol+4)*BS_STR + col]);
                #pragma unroll
                for (int mt = 0; mt < 4; mt++)
                    mma_tf32(acc[mt][nt], af[mt], bf);
            }
        }
        __syncthreads();
    }

    #pragma unroll
    for (int mt = 0; mt < 4; mt++) {
        int row = by*128 + wm*64 + mt*16 + (lane >> 2);
        #pragma unroll
        for (int nt = 0; nt < 4; nt++) {
            int col = bx*128 + wn*32 + nt*8 + 2*(lane & 3);
            float v0 = acc[mt][nt][0], v1 = acc[mt][nt][1];
            float v2 = acc[mt][nt][2], v3 = acc[mt][nt][3];
            if (roundC) { v0 = f2tf32f(v0); v1 = f2tf32f(v1); v2 = f2tf32f(v2); v3 = f2tf32f(v3); }
            *(float2*)&C[(size_t)row*N + col]     = make_float2(v0, v1);
            *(float2*)&C[(size_t)(row+8)*N + col] = make_float2(v2, v3);
        }
    }
}

// ---------------- RMSNorm (rounds output) ----------------
__global__ __launch_bounds__(128) void rmsnorm_kernel(const float* __restrict__ w) {
    int row = blockIdx.x;
    const float* x = g_kva + (size_t)row * KVAN;
    float* y = g_ckv + (size_t)row * RANKn;
    int tid = threadIdx.x;
    float4 v = *(const float4*)&x[tid*4];
    float ss = v.x*v.x + v.y*v.y + v.z*v.z + v.w*v.w;
    #pragma unroll
    for (int off = 16; off >= 1; off >>= 1)
        ss += __shfl_xor_sync(0xffffffffu, ss, off);
    __shared__ float warp_s[4];
    if ((tid & 31) == 0) warp_s[tid >> 5] = ss;
    __syncthreads();
    float total = warp_s[0] + warp_s[1] + warp_s[2] + warp_s[3];
    float inv = rsqrtf(total * (1.0f/(float)RANKn) + 1e-6f);
    float4 wv = *(const float4*)&w[tid*4];
    *(float4*)&y[tid*4] = make_float4(f2tf32f(v.x*wv.x*inv), f2tf32f(v.y*wv.y*inv),
                                      f2tf32f(v.z*wv.z*inv), f2tf32f(v.w*wv.w*inv));
}

// ---------------- RoPE q (in place): rotate, *ATTN_SCALE, round ----------------
__global__ __launch_bounds__(256) void rope_q_kernel(const int* __restrict__ pos_ids) {
    int t = blockIdx.x * 4 + (threadIdx.x >> 6);
    int d = threadIdx.x & 63;
    int bs = t >> 4;
    float p = (float)pos_ids[bs];
    float f = p * g_invfreq[d];
    float sv, cv;
    sincosf(f, &sv, &cv);
    cv *= MSCALE_F; sv *= MSCALE_F;
    float* q = g_q + (size_t)t * Dn;
    float x0 = q[d], x1 = q[d+64];
    q[d]    = f2tf32f((x0*cv - x1*sv) * ATTN_SCALE);
    q[d+64] = f2tf32f((x1*cv + x0*sv) * ATTN_SCALE);
}

// ---------------- RoPE k_rope (raw out; rounded at flash fill) ----------------
__global__ __launch_bounds__(256) void rope_k_kernel(const int* __restrict__ pos_ids) {
    int bs = blockIdx.x * 4 + (threadIdx.x >> 6);
    int d = threadIdx.x & 63;
    float p = (float)pos_ids[bs];
    float f = p * g_invfreq[d];
    float sv, cv;
    sincosf(f, &sv, &cv);
    cv *= MSCALE_F; sv *= MSCALE_F;
    const float* kr = g_kva + (size_t)bs * KVAN + RANKn;
    float x0 = kr[d], x1 = kr[d+64];
    float* o = g_krope + (size_t)bs * Dn;
    o[d]    = x0*cv - x1*sv;
    o[d+64] = x1*cv + x0*sv;
}

// ---------------- tf32 flash attention, Q register-resident ----------------
// grid (S/64, B*H), 128 threads = 4 warps; warp w owns q-rows [w*16, w*16+16).
#define AT_STR 132
#define FLASH_SMEM_BYTES (2*64*AT_STR*4)

__global__ __launch_bounds__(128) void flash_tf32_kernel() {
    extern __shared__ float smf[];
    float* Ks = smf;
    float* Vs = Ks + 64*AT_STR;

    int tid = threadIdx.x;
    int lane = tid & 31, w = tid >> 5;
    int qt = blockIdx.x;
    int bh = blockIdx.y;
    int b = bh >> 4, h = bh & 15;

    const int r0 = w*16 + (lane >> 2);

    // stage Q through Ks, then pull fragments into registers (g_q already scaled+rounded)
    const float* qbase = g_q + ((size_t)(b*Sn + qt*64)) * HDn + h*Dn;
    #pragma unroll
    for (int l = 0; l < 16; l++) {
        int i = tid + l*128;
        int r = i >> 5, d4 = (i & 31) << 2;
        *(float4*)&Ks[r*AT_STR + d4] = *(const float4*)&qbase[(size_t)r*HDn + d4];
    }
    __syncthreads();
    unsigned qf[16][4];
    #pragma unroll
    for (int ks = 0; ks < 16; ks++) {
        int kcol = ks*8 + (lane & 3);
        qf[ks][0] = __float_as_uint(Ks[r0*AT_STR + kcol]);
        qf[ks][1] = __float_as_uint(Ks[(r0+8)*AT_STR + kcol]);
        qf[ks][2] = __float_as_uint(Ks[r0*AT_STR + kcol + 4]);
        qf[ks][3] = __float_as_uint(Ks[(r0+8)*AT_STR + kcol + 4]);
    }

    float o[16][4];
    float m0 = -1e30f, m1 = -1e30f, l0 = 0.f, l1 = 0.f;
    #pragma unroll
    for (int nt = 0; nt < 16; nt++)
        #pragma unroll
        for (int r = 0; r < 4; r++) o[nt][r] = 0.f;

    const int s1 = (lane & 28) | ((lane >> 1) & 1);
    const int s2 = s1 | 2;
    const bool odd = (lane & 1);

    for (int kt = 0; kt <= qt; kt++) {
        __syncthreads();
        // fill K (= kv_nope + krope, rounded) and V (already rounded) from g_kv/g_krope
        size_t tok0 = (size_t)(b*Sn + kt*64);
        #pragma unroll
        for (int l = 0; l < 16; l++) {
            int i = tid + l*128;
            int r = i >> 5, d4 = (i & 31) << 2;
            size_t base = (tok0 + r)*((size_t)Hn*2*Dn) + h*256;
            float4 kn = *(const float4*)&g_kv[base + d4];
            float4 kr = *(const float4*)&g_krope[(tok0 + r)*Dn + d4];
            *(float4*)&Ks[r*AT_STR + d4] = make_float4(
                f2tf32f(kn.x + kr.x), f2tf32f(kn.y + kr.y),
                f2tf32f(kn.z + kr.z), f2tf32f(kn.w + kr.w));
            *(float4*)&Vs[r*AT_STR + d4] = *(const float4*)&g_kv[base + 128 + d4];
        }
        __syncthreads();

        // S = Q @ K^T
        float sacc[8][4];
        #pragma unroll
        for (int nt = 0; nt < 8; nt++)
            #pragma unroll
            for (int r = 0; r < 4; r++) sacc[nt][r] = 0.f;

        #pragma unroll
        for (int ks = 0; ks < 16; ks++) {
            int kcol = ks*8 + (lane & 3);
            #pragma unroll
            for (int nt = 0; nt < 8; nt++) {
                int n = nt*8 + (lane >> 2);
                unsigned bf[2];
                bf[0] = __float_as_uint(Ks[n*AT_STR + kcol]);
                bf[1] = __float_as_uint(Ks[n*AT_STR + kcol + 4]);
                mma_tf32(sacc[nt], qf[ks], bf);
            }
        }

        if (kt == qt) {
            #pragma unroll
            for (int nt = 0; nt < 8; nt++) {
                int c = nt*8 + 2*(lane & 3);
                if (c     > r0)   sacc[nt][0] = -1e30f;
                if (c + 1 > r0)   sacc[nt][1] = -1e30f;
                if (c     > r0+8) sacc[nt][2] = -1e30f;
                if (c + 1 > r0+8) sacc[nt][3] = -1e30f;
            }
        }

        // online softmax
        float mx0 = -1e30f, mx1 = -1e30f;
        #pragma unroll
        for (int nt = 0; nt < 8; nt++) {
            mx0 = fmaxf(mx0, fmaxf(sacc[nt][0], sacc[nt][1]));
            mx1 = fmaxf(mx1, fmaxf(sacc[nt][2], sacc[nt][3]));
        }
        mx0 = fmaxf(mx0, __shfl_xor_sync(0xffffffffu, mx0, 1));
        mx0 = fmaxf(mx0, __shfl_xor_sync(0xffffffffu, mx0, 2));
        mx1 = fmaxf(mx1, __shfl_xor_sync(0xffffffffu, mx1, 1));
        mx1 = fmaxf(mx1, __shfl_xor_sync(0xffffffffu, mx1, 2));
        float mn0 = fmaxf(m0, mx0), mn1 = fmaxf(m1, mx1);
        float corr0 = __expf(m0 - mn0), corr1 = __expf(m1 - mn1);
        m0 = mn0; m1 = mn1;

        float sum0 = 0.f, sum1 = 0.f;
        #pragma unroll
        for (int nt = 0; nt < 8; nt++) {
            sacc[nt][0] = __expf(sacc[nt][0] - mn0);
            sacc[nt][1] = __expf(sacc[nt][1] - mn0);
            sacc[nt][2] = __expf(sacc[nt][2] - mn1);
            sacc[nt][3] = __expf(sacc[nt][3] - mn1);
            sum0 += sacc[nt][0] + sacc[nt][1];
            sum1 += sacc[nt][2] + sacc[nt][3];
        }
        sum0 += __shfl_xor_sync(0xffffffffu, sum0, 1);
        sum0 += __shfl_xor_sync(0xffffffffu, sum0, 2);
        sum1 += __shfl_xor_sync(0xffffffffu, sum1, 1);
        sum1 += __shfl_xor_sync(0xffffffffu, sum1, 2);
        l0 = l0*corr0 + sum0;
        l1 = l1*corr1 + sum1;

        #pragma unroll
        for (int nt = 0; nt < 16; nt++) {
            o[nt][0] *= corr0; o[nt][1] *= corr0;
            o[nt][2] *= corr1; o[nt][3] *= corr1;
        }

        // O += P @ V
        #pragma unroll
        for (int kc = 0; kc < 8; kc++) {
            unsigned pa[4];
            float v0, v1;
            v0 = __shfl_sync(0xffffffffu, sacc[kc][0], s1);
            v1 = __shfl_sync(0xffffffffu, sacc[kc][1], s1);
            pa[0] = f2tf32(odd ? v1 : v0);
            v0 = __shfl_sync(0xffffffffu, sacc[kc][2], s1);
            v1 = __shfl_sync(0xffffffffu, sacc[kc][3], s1);
            pa[1] = f2tf32(odd ? v1 : v0);
            v0 = __shfl_sync(0xffffffffu, sacc[kc][0], s2);
            v1 = __shfl_sync(0xffffffffu, sacc[kc][1], s2);
            pa[2] = f2tf32(odd ? v1 : v0);
            v0 = __shfl_sync(0xffffffffu, sacc[kc][2], s2);
            v1 = __shfl_sync(0xffffffffu, sacc[kc][3], s2);
            pa[3] = f2tf32(odd ? v1 : v0);

            int kr = kc*8 + (lane & 3);
            #pragma unroll
            for (int nt = 0; nt < 16; nt++) {
                int d = nt*8 + (lane >> 2);
                unsigned bf[2];
                bf[0] = __float_as_uint(Vs[kr*AT_STR + d]);
                bf[1] = __float_as_uint(Vs[(kr+4)*AT_STR + d]);
                mma_tf32(o[nt], pa, bf);
            }
        }
    }

    // epilogue (rounded: feeds tf32 o-proj GEMM)
    float inv0 = 1.0f / (l0 + 1e-5f);
    float inv1 = 1.0f / (l1 + 1e-5f);
    size_t row0 = (size_t)(b*Sn + qt*64 + r0);
    float* op0 = g_attn + row0*HDn + h*Dn;
    float* op1 = g_attn + (row0+8)*HDn + h*Dn;
    #pragma unroll
    for (int nt = 0; nt < 16; nt++) {
        int d = nt*8 + 2*(lane & 3);
        *(float2*)&op0[d] = make_float2(f2tf32f(o[nt][0]*inv0), f2tf32f(o[nt][1]*inv0));
        *(float2*)&op1[d] = make_float2(f2tf32f(o[nt][2]*inv1), f2tf32f(o[nt][3]*inv1));
    }
}

// ---------------- launch ----------------
extern "C" void kernel_launch(void* const* d_in, const int* in_sizes, int n_in,
                              void* d_out, int out_size) {
    const float* hidden  = (const float*)d_in[0];
    const int*   pos_ids = (const int*)  d_in[1];
    const float* w_q     = (const float*)d_in[2];
    const float* w_kv_a  = (const float*)d_in[3];
    const float* w_kv_b  = (const float*)d_in[4];
    const float* w_o     = (const float*)d_in[5];
    const float* kv_ln_w = (const float*)d_in[6];
    float* out = (float*)d_out;

    float *pq, *pckv, *pkv, *pattn;
    float *phid, *pwq, *pwkva, *pwkvb, *pwo;
    cudaGetSymbolAddress((void**)&pq,    g_q);
    cudaGetSymbolAddress((void**)&pckv,  g_ckv);
    cudaGetSymbolAddress((void**)&pkv,   g_kv);
    cudaGetSymbolAddress((void**)&pattn, g_attn);
    cudaGetSymbolAddress((void**)&phid,  g_hid_r);
    cudaGetSymbolAddress((void**)&pwq,   g_wq_r);
    cudaGetSymbolAddress((void**)&pwkva, g_wkva_r);
    cudaGetSymbolAddress((void**)&pwkvb, g_wkvb_r);
    cudaGetSymbolAddress((void**)&pwo,   g_wo_r);
    float* pkva;
    cudaGetSymbolAddress((void**)&pkva,  g_kva);

    cudaFuncSetAttribute(flash_tf32_kernel, cudaFuncAttributeMaxDynamicSharedMemorySize,
                         FLASH_SMEM_BYTES);
    cudaFuncSetAttribute(gemm_tf32, cudaFuncAttributeMaxDynamicSharedMemorySize,
                         GEMM_SMEM_BYTES);

    init_invfreq_kernel<<<1, 64>>>();

    // pre-round inputs to tf32 (eliminates all in-loop cvt)
    round_copy_kernel<<<(BSn*HIDn/4 + 255)/256, 256>>>(hidden, phid, BSn*HIDn/4);
    round_copy_kernel<<<(HIDn*HDn/4 + 255)/256, 256>>>(w_q, pwq, HIDn*HDn/4);
    round_copy_kernel<<<(HIDn*KVAN/4 + 255)/256, 256>>>(w_kv_a, pwkva, HIDn*KVAN/4);
    round_copy_kernel<<<(RANKn*Hn*2*Dn/4 + 255)/256, 256>>>(w_kv_b, pwkvb, RANKn*Hn*2*Dn/4);
    round_copy_kernel<<<(HDn*HIDn/4 + 255)/256, 256>>>(w_o, pwo, HDn*HIDn/4);

    // q = hidden @ w_q
    gemm_tf32<<<dim3(HDn/128, BSn/128), 256, GEMM_SMEM_BYTES>>>(phid, pwq, pq, BSn, HDn, HIDn, 0);
    // kv_a = hidden @ w_kv_a
    gemm_tf32<<<dim3(KVAN/128, BSn/128), 256, GEMM_SMEM_BYTES>>>(phid, pwkva, pkva, BSn, KVAN, HIDn, 0);

    rmsnorm_kernel<<<BSn, 128>>>(kv_ln_w);
    rope_k_kernel<<<BSn/4, 256>>>(pos_ids);

    // kv = ckv @ w_kv_b (rounded output: feeds attention)
    gemm_tf32<<<dim3((Hn*2*Dn)/128, BSn/128), 256, GEMM_SMEM_BYTES>>>(pckv, pwkvb, pkv, BSn, Hn*2*Dn, RANKn, 1);

    rope_q_kernel<<<(BSn*Hn)/4, 256>>>(pos_ids);

    flash_tf32_kernel<<<dim3(Sn/64, Bn*Hn), 128, FLASH_SMEM_BYTES>>>();

    // out = attn @ w_o (raw fp32 output)
    gemm_tf32<<<dim3(HIDn/128, BSn/128), 256, GEMM_SMEM_BYTES>>>(pattn, pwo, out, BSn, HIDn, HIDn, 0);
}

// round 7
// speedup vs baseline: 6.8933x; 2.1081x over previous
#include <cuda_runtime.h>
#include <cuda_fp16.h>
#include <math.h>

// ---------------- problem constants ----------------
#define Bn    2
#define Sn    2048
#define HIDn  2048
#define Hn    16
#define Dn    128
#define RANKn 512
#define BSn   (Bn*Sn)        // 4096
#define KVAN  (RANKn+Dn)     // 640
#define HDn   (Hn*Dn)        // 2048

#define MSCALE_F    1.2772588722239781f
#define ATTN_SCALE  0.08838834764831845f

// ---------------- scratch (half everywhere) ----------------
__device__ __half g_hid_h[(size_t)BSn*HIDn];
__device__ __half g_wq_t[(size_t)HDn*HIDn];        // [N=2048][K=2048]
__device__ __half g_wkva_t[(size_t)KVAN*HIDn];     // [640][2048]
__device__ __half g_wkvb_t[(size_t)Hn*2*Dn*RANKn]; // [4096][512]
__device__ __half g_wo_t[(size_t)HIDn*HDn];        // [2048][2048]
__device__ __half g_q_h[(size_t)BSn*HDn];
__device__ __half g_kva_h[(size_t)BSn*KVAN];
__device__ __half g_ckv_h[(size_t)BSn*RANKn];
__device__ __half g_kv_h[(size_t)BSn*Hn*2*Dn];
__device__ __half g_krope_h[(size_t)BSn*Dn];
__device__ __half g_attn_h[(size_t)BSn*HDn];
__device__ float  g_invfreq[Dn/2];

// ---------------- helpers ----------------
__device__ __forceinline__ unsigned h2u(float a, float b) {
    __half2 h = __floats2half2_rn(a, b);
    return *(unsigned*)&h;
}
__device__ __forceinline__ unsigned hadd2u(unsigned a, unsigned b) {
    __half2 r = __hadd2(*(__half2*)&a, *(__half2*)&b);
    return *(unsigned*)&r;
}

__device__ __forceinline__ void mma_f16(float* c, unsigned a0, unsigned a1, unsigned a2,
                                        unsigned a3, unsigned b0, unsigned b1) {
    asm volatile(
        "mma.sync.aligned.m16n8k16.row.col.f32.f16.f16.f32 "
        "{%0,%1,%2,%3}, {%4,%5,%6,%7}, {%8,%9}, {%0,%1,%2,%3};"
        : "+f"(c[0]), "+f"(c[1]), "+f"(c[2]), "+f"(c[3])
        : "r"(a0), "r"(a1), "r"(a2), "r"(a3), "r"(b0), "r"(b1));
}

__device__ __forceinline__ void ldsm4(unsigned& r0, unsigned& r1, unsigned& r2, unsigned& r3,
                                      const __half* p) {
    unsigned a = (unsigned)__cvta_generic_to_shared(p);
    asm volatile("ldmatrix.sync.aligned.m8n8.x4.shared.b16 {%0,%1,%2,%3}, [%4];"
        : "=r"(r0), "=r"(r1), "=r"(r2), "=r"(r3) : "r"(a));
}
__device__ __forceinline__ void ldsm4t(unsigned& r0, unsigned& r1, unsigned& r2, unsigned& r3,
                                       const __half* p) {
    unsigned a = (unsigned)__cvta_generic_to_shared(p);
    asm volatile("ldmatrix.sync.aligned.m8n8.x4.trans.shared.b16 {%0,%1,%2,%3}, [%4];"
        : "=r"(r0), "=r"(r1), "=r"(r2), "=r"(r3) : "r"(a));
}

__device__ __forceinline__ void cp16(void* smem_dst, const void* gmem_src) {
    unsigned d = (unsigned)__cvta_generic_to_shared(smem_dst);
    asm volatile("cp.async.cg.shared.global [%0], [%1], 16;" :: "r"(d), "l"(gmem_src));
}
__device__ __forceinline__ void cp_commit() { asm volatile("cp.async.commit_group;"); }
__device__ __forceinline__ void cp_wait0()  { asm volatile("cp.async.wait_group 0;"); }

// ---------------- f32 -> half copy (hidden) ----------------
__global__ __launch_bounds__(256) void round_half_kernel(const float* __restrict__ src,
                                                         __half* __restrict__ dst, int n4) {
    int i = blockIdx.x * 256 + threadIdx.x;
    if (i >= n4) return;
    float4 v = ((const float4*)src)[i];
    uint2 o;
    o.x = h2u(v.x, v.y);
    o.y = h2u(v.z, v.w);
    ((uint2*)dst)[i] = o;
}

// ---------------- transpose + halve weights: src[K][N] f32 -> dst[N][K] half ----------------
__global__ __launch_bounds__(256) void transpose_half_kernel(const float* __restrict__ src,
                                                             __half* __restrict__ dst,
                                                             int K, int N) {
    __shared__ float tile[32][33];
    int k0 = blockIdx.y * 32, n0 = blockIdx.x * 32;
    int tx = threadIdx.x & 31, ty = threadIdx.x >> 5;   // 32 x 8
    #pragma unroll
    for (int j = 0; j < 32; j += 8)
        tile[ty + j][tx] = src[(size_t)(k0 + ty + j) * N + n0 + tx];
    __syncthreads();
    #pragma unroll
    for (int j = 0; j < 32; j += 8)
        dst[(size_t)(n0 + ty + j) * K + k0 + tx] = __float2half_rn(tile[tx][ty + j]);
}

// ---------------- YaRN inv_freq ----------------
__global__ void init_invfreq_kernel() {
    int i = threadIdx.x;
    if (i >= Dn/2) return;
    const double base = 500000.0;
    const double two_pi = 6.283185307179586;
    double pf = exp(((double)(2*i) / (double)Dn) * log(base));
    double extrap = 1.0 / pf;
    double interp = 1.0 / (16.0 * pf);
    double lowf  = floor((double)Dn * log(8192.0 / (32.0 * two_pi)) / (2.0 * log(base)));
    double highf = ceil ((double)Dn * log(8192.0 / ( 1.0 * two_pi)) / (2.0 * log(base)));
    if (lowf < 0.0) lowf = 0.0;
    if (highf > (double)(Dn-1)) highf = (double)(Dn-1);
    double denom = highf - lowf;
    if (denom < 1.0) denom = 1.0;
    double sm = ((double)i - lowf) / denom;
    sm = fmin(fmax(sm, 0.0), 1.0);
    g_invfreq[i] = (float)((1.0 - sm) * interp + sm * extrap);
}

// ---------------- fp16 GEMM: C[M,N] = A[M,K] @ Bt[N,K]^T ----------------
// BM=128, BN=128, BK=64 halves, 256 threads (8 warps 2x4, warp tile 64x32).
// 2-stage cp.async. A,Bt half. outHalf: C is __half*, else float*.
#define GSTR 72                    // smem row stride (halves): 72/2=36 == 4 mod 32
#define G_STAGE (128*GSTR)         // halves per stage (A or B)
#define GEMM_SMEM_BYTES (4*G_STAGE*2)

__global__ __launch_bounds__(256) void gemm_f16(const __half* __restrict__ A,
                                                const __half* __restrict__ Bt,
                                                void* __restrict__ Cv,
                                                int M, int N, int K, int outHalf) {
    extern __shared__ __half smh[];
    __half* As = smh;                       // [2][128][GSTR]
    __half* Bs = smh + 2*G_STAGE;           // [2][128][GSTR]

    int tid = threadIdx.x;
    int lane = tid & 31, warp = tid >> 5;
    int wm = warp >> 2, wn = warp & 3;
    int bx = blockIdx.x, by = blockIdx.y;

    const int ar  = tid >> 3;            // 0..31 (4 passes of 32 rows)
    const int ac8 = (tid & 7) << 3;      // halves 0..56

    const __half* Abase = A  + (size_t)(by*128)*K;
    const __half* Bbase = Bt + (size_t)(bx*128)*K;

    float acc[4][4][4];
    #pragma unroll
    for (int i = 0; i < 4; i++)
        #pragma unroll
        for (int j = 0; j < 4; j++)
            #pragma unroll
            for (int r = 0; r < 4; r++) acc[i][j][r] = 0.f;

    int T = K >> 6;

    // prologue
    #pragma unroll
    for (int l = 0; l < 4; l++) {
        int row = ar + l*32;
        cp16(&As[row*GSTR + ac8], &Abase[(size_t)row*K + ac8]);
        cp16(&Bs[row*GSTR + ac8], &Bbase[(size_t)row*K + ac8]);
    }
    cp_commit();

    // ldmatrix lane addressing precompute
    const int lm = lane >> 3;            // matrix id 0..3
    const int lr = lane & 7;             // row within matrix

    for (int t = 0; t < T; t++) {
        cp_wait0();
        __syncthreads();
        int st = t & 1;
        if (t + 1 < T) {
            int kt = (t + 1) << 6;
            __half* Ad = As + (st ^ 1)*G_STAGE;
            __half* Bd = Bs + (st ^ 1)*G_STAGE;
            #pragma unroll
            for (int l = 0; l < 4; l++) {
                int row = ar + l*32;
                cp16(&Ad[row*GSTR + ac8], &Abase[(size_t)row*K + kt + ac8]);
                cp16(&Bd[row*GSTR + ac8], &Bbase[(size_t)row*K + kt + ac8]);
            }
            cp_commit();
        }
        const __half* As_ = As + st*G_STAGE;
        const __half* Bs_ = Bs + st*G_STAGE;

        #pragma unroll
        for (int ks = 0; ks < 4; ks++) {
            int k0 = ks*16;
            // A frags: per mt, x4 ldmatrix (m0: r0-7 klo, m1: r8-15 klo, m2: r0-7 khi, m3: r8-15 khi)
            unsigned af[4][4];
            #pragma unroll
            for (int mt = 0; mt < 4; mt++) {
                int row = wm*64 + mt*16 + (lm & 1)*8 + lr;
                int col = k0 + (lm >> 1)*8;
                ldsm4(af[mt][0], af[mt][1], af[mt][2], af[mt][3], &As_[row*GSTR + col]);
            }
            // B frags: per ntp (pair of n8 tiles), x4 (m0: n-lo klo -> b0 nt_e, m1: n-lo khi -> b1 nt_e,
            //                                         m2: n-hi klo -> b0 nt_o, m3: n-hi khi -> b1 nt_o)
            #pragma unroll
            for (int ntp = 0; ntp < 2; ntp++) {
                int nrow = wn*32 + ntp*16 + (lm >> 1)*8 + lr;
                int col  = k0 + (lm & 1)*8;
                unsigned b0, b1, b2, b3;
                ldsm4(b0, b1, b2, b3, &Bs_[nrow*GSTR + col]);
                #pragma unroll
                for (int mt = 0; mt < 4; mt++) {
                    mma_f16(acc[mt][ntp*2],   af[mt][0], af[mt][1], af[mt][2], af[mt][3], b0, b1);
                    mma_f16(acc[mt][ntp*2+1], af[mt][0], af[mt][1], af[mt][2], af[mt][3], b2, b3);
                }
            }
        }
        __syncthreads();
    }

    // epilogue
    if (outHalf) {
        __half* C = (__half*)Cv;
        #pragma unroll
        for (int mt = 0; mt < 4; mt++) {
            int row = by*128 + wm*64 + mt*16 + (lane >> 2);
            #pragma unroll
            for (int nt = 0; nt < 4; nt++) {
                int col = bx*128 + wn*32 + nt*8 + 2*(lane & 3);
                *(unsigned*)&C[(size_t)row*N + col]     = h2u(acc[mt][nt][0], acc[mt][nt][1]);
                *(unsigned*)&C[(size_t)(row+8)*N + col] = h2u(acc[mt][nt][2], acc[mt][nt][3]);
            }
        }
    } else {
        float* C = (float*)Cv;
        #pragma unroll
        for (int mt = 0; mt < 4; mt++) {
            int row = by*128 + wm*64 + mt*16 + (lane >> 2);
            #pragma unroll
            for (int nt = 0; nt < 4; nt++) {
                int col = bx*128 + wn*32 + nt*8 + 2*(lane & 3);
                *(float2*)&C[(size_t)row*N + col]     = make_float2(acc[mt][nt][0], acc[mt][nt][1]);
                *(float2*)&C[(size_t)(row+8)*N + col] = make_float2(acc[mt][nt][2], acc[mt][nt][3]);
            }
        }
    }
}

// ---------------- RMSNorm: g_kva_h[:, :512] -> g_ckv_h ----------------
__global__ __launch_bounds__(128) void rmsnorm_kernel(const float* __restrict__ w) {
    int row = blockIdx.x;
    const __half* x = g_kva_h + (size_t)row * KVAN;
    __half* y = g_ckv_h + (size_t)row * RANKn;
    int tid = threadIdx.x;
    uint2 u = *(const uint2*)&x[tid*4];
    __half2 h0 = *(__half2*)&u.x, h1 = *(__half2*)&u.y;
    float f0 = __low2float(h0), f1 = __high2float(h0);
    float f2 = __low2float(h1), f3 = __high2float(h1);
    float ss = f0*f0 + f1*f1 + f2*f2 + f3*f3;
    #pragma unroll
    for (int off = 16; off >= 1; off >>= 1)
        ss += __shfl_xor_sync(0xffffffffu, ss, off);
    __shared__ float warp_s[4];
    if ((tid & 31) == 0) warp_s[tid >> 5] = ss;
    __syncthreads();
    float total = warp_s[0] + warp_s[1] + warp_s[2] + warp_s[3];
    float inv = rsqrtf(total * (1.0f/(float)RANKn) + 1e-6f);
    float4 wv = *(const float4*)&w[tid*4];
    uint2 o;
    o.x = h2u(f0*wv.x*inv, f1*wv.y*inv);
    o.y = h2u(f2*wv.z*inv, f3*wv.w*inv);
    *(uint2*)&y[tid*4] = o;
}

// ---------------- RoPE q (half in/out, *ATTN_SCALE) ----------------
__global__ __launch_bounds__(256) void rope_q_kernel(const int* __restrict__ pos_ids) {
    int t = blockIdx.x * 4 + (threadIdx.x >> 6);
    int d = threadIdx.x & 63;
    int bs = t >> 4;
    float p = (float)pos_ids[bs];
    float f = p * g_invfreq[d];
    float sv, cv;
    sincosf(f, &sv, &cv);
    cv *= MSCALE_F; sv *= MSCALE_F;
    __half* q = g_q_h + (size_t)t * Dn;
    float x0 = __half2float(q[d]), x1 = __half2float(q[d+64]);
    q[d]    = __float2half_rn((x0*cv - x1*sv) * ATTN_SCALE);
    q[d+64] = __float2half_rn((x1*cv + x0*sv) * ATTN_SCALE);
}

// ---------------- RoPE k_rope (half out) ----------------
__global__ __launch_bounds__(256) void rope_k_kernel(const int* __restrict__ pos_ids) {
    int bs = blockIdx.x * 4 + (threadIdx.x >> 6);
    int d = threadIdx.x & 63;
    float p = (float)pos_ids[bs];
    float f = p * g_invfreq[d];
    float sv, cv;
    sincosf(f, &sv, &cv);
    cv *= MSCALE_F; sv *= MSCALE_F;
    const __half* kr = g_kva_h + (size_t)bs * KVAN + RANKn;
    float x0 = __half2float(kr[d]), x1 = __half2float(kr[d+64]);
    __half* o = g_krope_h + (size_t)bs * Dn;
    o[d]    = __float2half_rn(x0*cv - x1*sv);
    o[d+64] = __float2half_rn(x1*cv + x0*sv);
}

// ---------------- fp16 flash attention ----------------
// grid (S/64, B*H), 128 threads = 4 warps; warp w owns q-rows [w*16, w*16+16).
// BM=BN=64, D=128. Ks/Vs half, stride 136 halves (136/2=68 == 4 mod 32).
#define KSTR 136
#define FLASH_SMEM_BYTES (2*64*KSTR*2)

__global__ __launch_bounds__(128) void flash_f16_kernel() {
    extern __shared__ __half smh[];
    __half* Ks = smh;
    __half* Vs = Ks + 64*KSTR;

    int tid = threadIdx.x;
    int lane = tid & 31, w = tid >> 5;
    int qt = gridDim.x - 1 - blockIdx.x;     // heavy tiles first
    int bh = blockIdx.y;
    int b = bh >> 4, h = bh & 15;

    const int lm = lane >> 3, lr = lane & 7;
    const int r0 = w*16 + (lane >> 2);

    // stage Q tile through Ks, then build A-fragments (8 x k16) via ldmatrix
    const __half* qbase = g_q_h + ((size_t)(b*Sn + qt*64)) * HDn + h*Dn;
    #pragma unroll
    for (int l = 0; l < 8; l++) {
        int i = tid + l*128;
        int r = i >> 4, d8 = (i & 15) << 3;
        *(uint4*)&Ks[r*KSTR + d8] = *(const uint4*)&qbase[(size_t)r*HDn + d8];
    }
    __syncthreads();
    unsigned qf[8][4];
    #pragma unroll
    for (int ks = 0; ks < 8; ks++) {
        int row = w*16 + (lm & 1)*8 + lr;
        int col = ks*16 + (lm >> 1)*8;
        ldsm4(qf[ks][0], qf[ks][1], qf[ks][2], qf[ks][3], &Ks[row*KSTR + col]);
    }

    float o[16][4];
    float m0 = -1e30f, m1 = -1e30f, l0 = 0.f, l1 = 0.f;
    #pragma unroll
    for (int nt = 0; nt < 16; nt++)
        #pragma unroll
        for (int r = 0; r < 4; r++) o[nt][r] = 0.f;

    for (int kt = 0; kt <= qt; kt++) {
        __syncthreads();
        size_t tok0 = (size_t)(b*Sn + kt*64);
        // V: async copy; K: manual (k_nope + k_rope in half)
        #pragma unroll
        for (int l = 0; l < 8; l++) {
            int i = tid + l*128;
            int r = i >> 4, d8 = (i & 15) << 3;
            size_t base = (tok0 + r)*((size_t)Hn*2*Dn) + h*256;
            cp16(&Vs[r*KSTR + d8], &g_kv_h[base + 128 + d8]);
            uint4 kn = *(const uint4*)&g_kv_h[base + d8];
            uint4 kr = *(const uint4*)&g_krope_h[(tok0 + r)*Dn + d8];
            uint4 ko;
            ko.x = hadd2u(kn.x, kr.x); ko.y = hadd2u(kn.y, kr.y);
            ko.z = hadd2u(kn.z, kr.z); ko.w = hadd2u(kn.w, kr.w);
            *(uint4*)&Ks[r*KSTR + d8] = ko;
        }
        cp_commit();
        cp_wait0();
        __syncthreads();

        // S = Q @ K^T : 8 k16-chunks x 8 key-tiles
        float sacc[8][4];
        #pragma unroll
        for (int nt = 0; nt < 8; nt++)
            #pragma unroll
            for (int r = 0; r < 4; r++) sacc[nt][r] = 0.f;

        #pragma unroll
        for (int ks = 0; ks < 8; ks++) {
            int k0 = ks*16;
            #pragma unroll
            for (int nt = 0; nt < 8; nt++) {
                int n = nt*8 + (lane >> 2);
                unsigned b0 = *(const unsigned*)&Ks[n*KSTR + k0 + 2*(lane & 3)];
                unsigned b1 = *(const unsigned*)&Ks[n*KSTR + k0 + 2*(lane & 3) + 8];
                mma_f16(sacc[nt], qf[ks][0], qf[ks][1], qf[ks][2], qf[ks][3], b0, b1);
            }
        }

        if (kt == qt) {   // diagonal mask
            #pragma unroll
            for (int nt = 0; nt < 8; nt++) {
                int c = nt*8 + 2*(lane & 3);
                if (c     > r0)   sacc[nt][0] = -1e30f;
                if (c + 1 > r0)   sacc[nt][1] = -1e30f;
                if (c     > r0+8) sacc[nt][2] = -1e30f;
                if (c + 1 > r0+8) sacc[nt][3] = -1e30f;
            }
        }

        // online softmax
        float mx0 = -1e30f, mx1 = -1e30f;
        #pragma unroll
        for (int nt = 0; nt < 8; nt++) {
            mx0 = fmaxf(mx0, fmaxf(sacc[nt][0], sacc[nt][1]));
            mx1 = fmaxf(mx1, fmaxf(sacc[nt][2], sacc[nt][3]));
        }
        mx0 = fmaxf(mx0, __shfl_xor_sync(0xffffffffu, mx0, 1));
        mx0 = fmaxf(mx0, __shfl_xor_sync(0xffffffffu, mx0, 2));
        mx1 = fmaxf(mx1, __shfl_xor_sync(0xffffffffu, mx1, 1));
        mx1 = fmaxf(mx1, __shfl_xor_sync(0xffffffffu, mx1, 2));
        float mn0 = fmaxf(m0, mx0), mn1 = fmaxf(m1, mx1);
        float corr0 = __expf(m0 - mn0), corr1 = __expf(m1 - mn1);
        m0 = mn0; m1 = mn1;

        float sum0 = 0.f, sum1 = 0.f;
        #pragma unroll
        for (int nt = 0; nt < 8; nt++) {
            sacc[nt][0] = __expf(sacc[nt][0] - mn0);
            sacc[nt][1] = __expf(sacc[nt][1] - mn0);
            sacc[nt][2] = __expf(sacc[nt][2] - mn1);
            sacc[nt][3] = __expf(sacc[nt][3] - mn1);
            sum0 += sacc[nt][0] + sacc[nt][1];
            sum1 += sacc[nt][2] + sacc[nt][3];
        }
        sum0 += __shfl_xor_sync(0xffffffffu, sum0, 1);
        sum0 += __shfl_xor_sync(0xffffffffu, sum0, 2);
        sum1 += __shfl_xor_sync(0xffffffffu, sum1, 1);
        sum1 += __shfl_xor_sync(0xffffffffu, sum1, 2);
        l0 = l0*corr0 + sum0;
        l1 = l1*corr1 + sum1;

        #pragma unroll
        for (int nt = 0; nt < 16; nt++) {
            o[nt][0] *= corr0; o[nt][1] *= corr0;
            o[nt][2] *= corr1; o[nt][3] *= corr1;
        }

        // O += P @ V : P packed straight from S C-frags (FA2 layout identity), V via ldmatrix.trans
        #pragma unroll
        for (int kc = 0; kc < 4; kc++) {
            unsigned pa0 = h2u(sacc[2*kc][0],   sacc[2*kc][1]);
            unsigned pa1 = h2u(sacc[2*kc][2],   sacc[2*kc][3]);
            unsigned pa2 = h2u(sacc[2*kc+1][0], sacc[2*kc+1][1]);
            unsigned pa3 = h2u(sacc[2*kc+1][2], sacc[2*kc+1][3]);
            int k0 = kc*16;
            #pragma unroll
            for (int dt = 0; dt < 8; dt++) {
                int n0 = dt*16;
                int vrow = k0 + (lm & 1)*8 + lr;
                int vcol = n0 + (lm >> 1)*8;
                unsigned b0, b1, b2, b3;
                ldsm4t(b0, b1, b2, b3, &Vs[vrow*KSTR + vcol]);
                mma_f16(o[2*dt],   pa0, pa1, pa2, pa3, b0, b1);
                mma_f16(o[2*dt+1], pa0, pa1, pa2, pa3, b2, b3);
            }
        }
    }

    // epilogue: half output for o-proj GEMM
    float inv0 = 1.0f / (l0 + 1e-5f);
    float inv1 = 1.0f / (l1 + 1e-5f);
    size_t row0 = (size_t)(b*Sn + qt*64 + r0);
    __half* op0 = g_attn_h + row0*HDn + h*Dn;
    __half* op1 = g_attn_h + (row0+8)*HDn + h*Dn;
    #pragma unroll
    for (int nt = 0; nt < 16; nt++) {
        int d = nt*8 + 2*(lane & 3);
        *(unsigned*)&op0[d] = h2u(o[nt][0]*inv0, o[nt][1]*inv0);
        *(unsigned*)&op1[d] = h2u(o[nt][2]*inv1, o[nt][3]*inv1);
    }
}

// ---------------- launch ----------------
extern "C" void kernel_launch(void* const* d_in, const int* in_sizes, int n_in,
                              void* d_out, int out_size) {
    const float* hidden  = (const float*)d_in[0];
    const int*   pos_ids = (const int*)  d_in[1];
    const float* w_q     = (const float*)d_in[2];
    const float* w_kv_a  = (const float*)d_in[3];
    const float* w_kv_b  = (const float*)d_in[4];
    const float* w_o     = (const float*)d_in[5];
    const float* kv_ln_w = (const float*)d_in[6];
    float* out = (float*)d_out;

    __half *phid, *pwq, *pwkva, *pwkvb, *pwo;
    __half *pq, *pkva, *pckv, *pkv, *pattn;
    cudaGetSymbolAddress((void**)&phid,  g_hid_h);
    cudaGetSymbolAddress((void**)&pwq,   g_wq_t);
    cudaGetSymbolAddress((void**)&pwkva, g_wkva_t);
    cudaGetSymbolAddress((void**)&pwkvb, g_wkvb_t);
    cudaGetSymbolAddress((void**)&pwo,   g_wo_t);
    cudaGetSymbolAddress((void**)&pq,    g_q_h);
    cudaGetSymbolAddress((void**)&pkva,  g_kva_h);
    cudaGetSymbolAddress((void**)&pckv,  g_ckv_h);
    cudaGetSymbolAddress((void**)&pkv,   g_kv_h);
    cudaGetSymbolAddress((void**)&pattn, g_attn_h);

    cudaFuncSetAttribute(gemm_f16, cudaFuncAttributeMaxDynamicSharedMemorySize,
                         GEMM_SMEM_BYTES);
    cudaFuncSetAttribute(flash_f16_kernel, cudaFuncAttributeMaxDynamicSharedMemorySize,
                         FLASH_SMEM_BYTES);

    init_invfreq_kernel<<<1, 64>>>();                                              // 0
    round_half_kernel<<<(BSn*HIDn/4 + 255)/256, 256>>>(hidden, phid, BSn*HIDn/4);  // 1

    transpose_half_kernel<<<dim3(HDn/32, HIDn/32), 256>>>(w_q, pwq, HIDn, HDn);    // 2
    // q = hidden @ w_q : [4096, 2048]
    gemm_f16<<<dim3(HDn/128, BSn/128), 256, GEMM_SMEM_BYTES>>>(phid, pwq, pq, BSn, HDn, HIDn, 1);  // 3

    transpose_half_kernel<<<dim3(KVAN/32, HIDn/32), 256>>>(w_kv_a, pwkva, HIDn, KVAN);             // 4
    // kv_a = hidden @ w_kv_a : [4096, 640]   <-- ncu -s 5 lands here
    gemm_f16<<<dim3(KVAN/128, BSn/128), 256, GEMM_SMEM_BYTES>>>(phid, pwkva, pkva, BSn, KVAN, HIDn, 1); // 5

    rmsnorm_kernel<<<BSn, 128>>>(kv_ln_w);                                         // 6
    rope_k_kernel<<<BSn/4, 256>>>(pos_ids);                                        // 7

    transpose_half_kernel<<<dim3((Hn*2*Dn)/32, RANKn/32), 256>>>(w_kv_b, pwkvb, RANKn, Hn*2*Dn);   // 8
    // kv = ckv @ w_kv_b : [4096, 4096]
    gemm_f16<<<dim3((Hn*2*Dn)/128, BSn/128), 256, GEMM_SMEM_BYTES>>>(pckv, pwkvb, pkv, BSn, Hn*2*Dn, RANKn, 1); // 9

    rope_q_kernel<<<(BSn*Hn)/4, 256>>>(pos_ids);                                   // 10

    flash_f16_kernel<<<dim3(Sn/64, Bn*Hn), 128, FLASH_SMEM_BYTES>>>();             // 11

    transpose_half_kernel<<<dim3(HIDn/32, HDn/32), 256>>>(w_o, pwo, HDn, HIDn);    // 12
    // out = attn @ w_o : [4096, 2048] (f32 out)
    gemm_f16<<<dim3(HIDn/128, BSn/128), 256, GEMM_SMEM_BYTES>>>(pattn, pwo, out, BSn, HIDn, HIDn, 0); // 13
}